// round 1
// baseline (speedup 1.0000x reference)
#include <cuda_runtime.h>
#include <math.h>

// ---------------- problem constants ----------------
#define C_DIM   1152
#define NHEADS  16
#define HD      72
#define B_SZ    4
#define T_SZ    16
#define S_SZ    256
#define N_TOK   4096            // T*S
#define M_ROWS  16384           // B*N
#define SS_STRIDE 6912          // 6*C
#define SCALE_ATTN 0.11785113019775792f  // 72^-0.5

// ---------------- scratch (device globals; no runtime allocation) ----------------
__device__ float g_ss  [B_SZ * 6 * C_DIM];
__device__ float g_xm  [(size_t)M_ROWS * C_DIM];
__device__ float g_big [(size_t)M_ROWS * 4608];
__device__ float g_attn[(size_t)M_ROWS * C_DIM];
__device__ float g_kvc [480 * 2304];

// ---------------- ss = scale_shift_table + t.reshape(B,6,C) ----------------
__global__ void compute_ss_kernel(const float* __restrict__ t,
                                  const float* __restrict__ table,
                                  float* __restrict__ ss)
{
    int idx = blockIdx.x * blockDim.x + threadIdx.x;
    if (idx >= B_SZ * SS_STRIDE) return;
    int b = idx / SS_STRIDE;
    int r = idx - b * SS_STRIDE;   // i*C + c
    ss[idx] = table[r] + t[idx];
}

// ---------------- layernorm + t2i modulate ----------------
__global__ void ln_mod_kernel(const float* __restrict__ X, float* __restrict__ Y,
                              const float* __restrict__ ss, int shift_idx, int scale_idx)
{
    int row = blockIdx.x;
    int b = row >> 12;
    const float* xp = X + (size_t)row * C_DIM;
    float lsum = 0.f, lsq = 0.f;
    for (int i = threadIdx.x; i < C_DIM; i += 256) {
        float v = xp[i];
        lsum += v; lsq += v * v;
    }
    // reduce
    __shared__ float s_sum[8], s_sq[8];
    int lane = threadIdx.x & 31, warp = threadIdx.x >> 5;
    #pragma unroll
    for (int off = 16; off > 0; off >>= 1) {
        lsum += __shfl_down_sync(0xffffffffu, lsum, off);
        lsq  += __shfl_down_sync(0xffffffffu, lsq,  off);
    }
    if (lane == 0) { s_sum[warp] = lsum; s_sq[warp] = lsq; }
    __syncthreads();
    __shared__ float s_mu, s_rstd;
    if (threadIdx.x == 0) {
        float su = 0.f, sq = 0.f;
        #pragma unroll
        for (int w = 0; w < 8; w++) { su += s_sum[w]; sq += s_sq[w]; }
        float mu = su / (float)C_DIM;
        float var = sq / (float)C_DIM - mu * mu;
        s_mu = mu;
        s_rstd = rsqrtf(var + 1e-6f);
    }
    __syncthreads();
    float mu = s_mu, rstd = s_rstd;
    const float* sh = ss + (size_t)(b * 6 + shift_idx) * C_DIM;
    const float* sc = ss + (size_t)(b * 6 + scale_idx) * C_DIM;
    float* yp = Y + (size_t)row * C_DIM;
    for (int i = threadIdx.x; i < C_DIM; i += 256) {
        float v = (xp[i] - mu) * rstd;
        yp[i] = v * (1.f + sc[i]) + sh[i];
    }
}

// ---------------- SGEMM: C = A(MxK) @ W(KxN) + bias, with fused epilogues ----------------
// EPI 0: out = v
// EPI 1: out = Res + Gate[b,col] * v      (gate-residual)
// EPI 2: out = Res + v                    (plain residual)
// EPI 3: out = gelu_tanh(v)
template<int EPI>
__global__ __launch_bounds__(256)
void sgemm_kernel(const float* __restrict__ A, const float* __restrict__ Bm,
                  const float* __restrict__ bias, float* __restrict__ Cm,
                  int M, int N, int K,
                  const float* __restrict__ Res, const float* __restrict__ Gate)
{
    __shared__ float As[16][132];
    __shared__ float Bs[16][132];
    int tid = threadIdx.x;
    int bm = blockIdx.y * 128;
    int bn = blockIdx.x * 128;
    int tr = (tid >> 4) << 3;
    int tc = (tid & 15) << 3;
    int a_row = tid >> 2;
    int a_col = (tid & 3) << 2;
    int b_row = tid >> 5;
    int b_col = (tid & 31) << 2;
    float acc[8][8];
    #pragma unroll
    for (int i = 0; i < 8; i++)
        #pragma unroll
        for (int j = 0; j < 8; j++) acc[i][j] = 0.f;

    for (int k0 = 0; k0 < K; k0 += 16) {
        #pragma unroll
        for (int i = 0; i < 2; i++) {
            int r = a_row + i * 64;
            int gr = bm + r;
            float4 v = make_float4(0.f, 0.f, 0.f, 0.f);
            if (gr < M) v = *(const float4*)(A + (size_t)gr * K + k0 + a_col);
            As[a_col + 0][r] = v.x; As[a_col + 1][r] = v.y;
            As[a_col + 2][r] = v.z; As[a_col + 3][r] = v.w;
        }
        #pragma unroll
        for (int i = 0; i < 2; i++) {
            int r = b_row + i * 8;
            float4 v = *(const float4*)(Bm + (size_t)(k0 + r) * N + bn + b_col);
            *(float4*)&Bs[r][b_col] = v;
        }
        __syncthreads();
        #pragma unroll
        for (int k = 0; k < 16; k++) {
            float4 a0 = *(float4*)&As[k][tr];
            float4 a1 = *(float4*)&As[k][tr + 4];
            float4 b0 = *(float4*)&Bs[k][tc];
            float4 b1 = *(float4*)&Bs[k][tc + 4];
            float ar[8] = {a0.x, a0.y, a0.z, a0.w, a1.x, a1.y, a1.z, a1.w};
            float br[8] = {b0.x, b0.y, b0.z, b0.w, b1.x, b1.y, b1.z, b1.w};
            #pragma unroll
            for (int i = 0; i < 8; i++)
                #pragma unroll
                for (int j = 0; j < 8; j++)
                    acc[i][j] += ar[i] * br[j];
        }
        __syncthreads();
    }

    #pragma unroll
    for (int i = 0; i < 8; i++) {
        int row = bm + tr + i;
        if (row >= M) continue;
        int b = row >> 12;
        #pragma unroll
        for (int j = 0; j < 8; j++) {
            int col = bn + tc + j;
            float v = acc[i][j] + bias[col];
            size_t oidx = (size_t)row * N + col;
            if (EPI == 0) {
                Cm[oidx] = v;
            } else if (EPI == 1) {
                Cm[oidx] = Res[oidx] + Gate[(size_t)b * SS_STRIDE + col] * v;
            } else if (EPI == 2) {
                Cm[oidx] = Res[oidx] + v;
            } else {
                float t3 = v + 0.044715f * v * v * v;
                Cm[oidx] = 0.5f * v * (1.f + tanhf(0.79788456080286536f * t3));
            }
        }
    }
}

// ---------------- flash attention (non-causal), one thread per query row ----------------
// grid: (qtiles, heads, units); block 256. Each block: 256 queries, loop KV in KTILE chunks.
template<int KTILE>
__global__ __launch_bounds__(256, 1)
void flash_attn_kernel(const float* __restrict__ Qp, const float* __restrict__ Kp,
                       const float* __restrict__ Vp, float* __restrict__ Op,
                       int q_ld, int kv_ld, int o_ld,
                       int q_unit_stride, int kv_unit_stride, int kv_len)
{
    extern __shared__ float sm[];
    float* q_s = sm;                       // 256 x 73
    float* k_s = sm + 256 * 73;            // KTILE x 73
    float* v_s = k_s + KTILE * 73;         // KTILE x 73

    int u = blockIdx.z, h = blockIdx.y, qt = blockIdx.x;
    size_t qrow0 = (size_t)u * q_unit_stride + (size_t)qt * 256;
    size_t kvrow0 = (size_t)u * kv_unit_stride;
    int hc = h * HD;
    int tid = threadIdx.x;

    for (int idx = tid; idx < 256 * HD; idx += 256) {
        int i = idx / HD, d = idx - i * HD;
        q_s[i * 73 + d] = Qp[(qrow0 + i) * q_ld + hc + d];
    }
    __syncthreads();

    float o[HD];
    #pragma unroll
    for (int d = 0; d < HD; d++) o[d] = 0.f;
    float m = -1e30f, l = 0.f;

    for (int j0 = 0; j0 < kv_len; j0 += KTILE) {
        for (int idx = tid; idx < KTILE * HD; idx += 256) {
            int j = idx / HD, d = idx - j * HD;
            size_t rr = (kvrow0 + j0 + j) * (size_t)kv_ld + hc + d;
            k_s[j * 73 + d] = Kp[rr];
            v_s[j * 73 + d] = Vp[rr];
        }
        __syncthreads();

        float s[KTILE];
        #pragma unroll
        for (int j = 0; j < KTILE; j++) s[j] = 0.f;
        #pragma unroll 2
        for (int d = 0; d < HD; d++) {
            float qd = q_s[tid * 73 + d];
            #pragma unroll
            for (int j = 0; j < KTILE; j++)
                s[j] += qd * k_s[j * 73 + d];
        }
        float mt = m;
        #pragma unroll
        for (int j = 0; j < KTILE; j++) { s[j] *= SCALE_ATTN; mt = fmaxf(mt, s[j]); }
        float corr = __expf(m - mt);
        l *= corr;
        #pragma unroll
        for (int d = 0; d < HD; d++) o[d] *= corr;
        #pragma unroll
        for (int j = 0; j < KTILE; j++) { float p = __expf(s[j] - mt); l += p; s[j] = p; }
        #pragma unroll 2
        for (int d = 0; d < HD; d++) {
            float a = o[d];
            #pragma unroll
            for (int j = 0; j < KTILE; j++)
                a += s[j] * v_s[j * 73 + d];
            o[d] = a;
        }
        m = mt;
        __syncthreads();
    }

    float inv = 1.f / l;
    float* op = Op + (qrow0 + tid) * (size_t)o_ld + hc;
    #pragma unroll
    for (int d = 0; d < HD; d++) op[d] = o[d] * inv;
}

// ---------------- RoPE in-place on q,k halves of temporal qkv ----------------
__global__ void rope_kernel(float* __restrict__ qkv,
                            const float* __restrict__ cosb, const float* __restrict__ sinb)
{
    int idx = blockIdx.x * blockDim.x + threadIdx.x;   // M_ROWS*16*36
    if (idx >= M_ROWS * NHEADS * 36) return;
    int d2 = idx % 36;
    int h  = (idx / 36) % NHEADS;
    int r  = idx / (36 * NHEADS);
    int t  = (r >> 8) & 15;          // row = b*4096 + t*256 + s
    float c = cosb[t * 36 + d2];
    float s = sinb[t * 36 + d2];
    size_t base = (size_t)r * 3456 + h * HD + 2 * d2;
    float qe = qkv[base], qo = qkv[base + 1];
    qkv[base]     = qe * c - qo * s;
    qkv[base + 1] = qe * s + qo * c;
    float ke = qkv[base + 1152], ko = qkv[base + 1153];
    qkv[base + 1152] = ke * c - ko * s;
    qkv[base + 1153] = ke * s + ko * c;
}

// ---------------- temporal causal attention: one thread per (b,s,h,tq) ----------------
__global__ void temporal_attn_kernel(const float* __restrict__ qkv, float* __restrict__ O)
{
    int idx = blockIdx.x * blockDim.x + threadIdx.x;   // 262144
    int tq = idx & 15;
    int h  = (idx >> 4) & 15;
    int s  = (idx >> 8) & 255;
    int b  = idx >> 16;
    size_t rowq = (size_t)b * N_TOK + (size_t)tq * 256 + s;
    const float* qp = qkv + rowq * 3456 + h * HD;
    float q[HD];
    #pragma unroll
    for (int d = 0; d < HD; d++) q[d] = qp[d];

    float sc[T_SZ];
    float m = -1e30f;
    #pragma unroll
    for (int tk = 0; tk < T_SZ; tk++) {
        const float* kp = qkv + ((size_t)b * N_TOK + (size_t)tk * 256 + s) * 3456 + 1152 + h * HD;
        float a = 0.f;
        #pragma unroll
        for (int d = 0; d < HD; d++) a += q[d] * kp[d];
        a *= SCALE_ATTN;
        if (tk > tq) a = -1e30f;
        sc[tk] = a;
        m = fmaxf(m, a);
    }
    float l = 0.f;
    #pragma unroll
    for (int tk = 0; tk < T_SZ; tk++) { sc[tk] = __expf(sc[tk] - m); l += sc[tk]; }
    float inv = 1.f / l;

    float* op = O + rowq * C_DIM + h * HD;
    #pragma unroll 2
    for (int d = 0; d < HD; d++) {
        float a = 0.f;
        #pragma unroll
        for (int tk = 0; tk < T_SZ; tk++)
            a += sc[tk] * qkv[((size_t)b * N_TOK + (size_t)tk * 256 + s) * 3456 + 2304 + h * HD + d];
        op[d] = a * inv;
    }
}

// ---------------- host orchestration ----------------
extern "C" void kernel_launch(void* const* d_in, const int* in_sizes, int n_in,
                              void* d_out, int out_size)
{
    (void)in_sizes; (void)n_in; (void)out_size;
    const float* x_in   = (const float*)d_in[0];
    const float* y_in   = (const float*)d_in[1];
    const float* t_in   = (const float*)d_in[2];
    const float* sstab  = (const float*)d_in[3];
    const float* w_qkv_s = (const float*)d_in[4];
    const float* b_qkv_s = (const float*)d_in[5];
    const float* w_proj_s = (const float*)d_in[6];
    const float* b_proj_s = (const float*)d_in[7];
    const float* w_qkv_t = (const float*)d_in[8];
    const float* b_qkv_t = (const float*)d_in[9];
    const float* w_proj_t = (const float*)d_in[10];
    const float* b_proj_t = (const float*)d_in[11];
    const float* wq_c  = (const float*)d_in[12];
    const float* bq_c  = (const float*)d_in[13];
    const float* wkv_c = (const float*)d_in[14];
    const float* bkv_c = (const float*)d_in[15];
    const float* wo_c  = (const float*)d_in[16];
    const float* bo_c  = (const float*)d_in[17];
    const float* w_fc1 = (const float*)d_in[18];
    const float* b_fc1 = (const float*)d_in[19];
    const float* w_fc2 = (const float*)d_in[20];
    const float* b_fc2 = (const float*)d_in[21];
    const float* f_cos = (const float*)d_in[22];
    const float* f_sin = (const float*)d_in[23];
    float* out = (float*)d_out;

    float *ss, *xm, *big, *attn, *kvc;
    cudaGetSymbolAddress((void**)&ss,   g_ss);
    cudaGetSymbolAddress((void**)&xm,   g_xm);
    cudaGetSymbolAddress((void**)&big,  g_big);
    cudaGetSymbolAddress((void**)&attn, g_attn);
    cudaGetSymbolAddress((void**)&kvc,  g_kvc);

    const int SPA_SMEM = (256 * 73 + 2 * 32 * 73) * 4;
    const int CRS_SMEM = (256 * 73 + 2 * 30 * 73) * 4;
    cudaFuncSetAttribute(flash_attn_kernel<32>, cudaFuncAttributeMaxDynamicSharedMemorySize, SPA_SMEM);
    cudaFuncSetAttribute(flash_attn_kernel<30>, cudaFuncAttributeMaxDynamicSharedMemorySize, CRS_SMEM);

    // 1) modulation vectors
    compute_ss_kernel<<<(B_SZ * SS_STRIDE + 255) / 256, 256>>>(t_in, sstab, ss);

    // 2) x_m = modulate(LN(x), shift_msa, scale_msa)
    ln_mod_kernel<<<M_ROWS, 256>>>(x_in, xm, ss, 0, 1);

    // 3) spatial: qkv = x_m @ w_qkv_s + b
    sgemm_kernel<0><<<dim3(27, 128), 256>>>(xm, w_qkv_s, b_qkv_s, big, M_ROWS, 3456, 1152, nullptr, nullptr);
    // 4) spatial attention (64 units x 16 heads, seq 256)
    flash_attn_kernel<32><<<dim3(1, 16, 64), 256, SPA_SMEM>>>(
        big, big + 1152, big + 2304, attn, 3456, 3456, 1152, 256, 256, 256);
    // 5) x = x + gate_msa * (attn @ w_proj_s + b)
    sgemm_kernel<1><<<dim3(9, 128), 256>>>(attn, w_proj_s, b_proj_s, out, M_ROWS, 1152, 1152,
                                           x_in, ss + 2 * C_DIM);

    // 6) temporal: qkv = x @ w_qkv_t + b
    sgemm_kernel<0><<<dim3(27, 128), 256>>>(out, w_qkv_t, b_qkv_t, big, M_ROWS, 3456, 1152, nullptr, nullptr);
    // 7) RoPE on q,k
    rope_kernel<<<(M_ROWS * NHEADS * 36 + 255) / 256, 256>>>(big, f_cos, f_sin);
    // 8) causal temporal attention
    temporal_attn_kernel<<<1024, 256>>>(big, attn);
    // 9) x = x + gate_msa * (attn @ w_proj_t + b)
    sgemm_kernel<1><<<dim3(9, 128), 256>>>(attn, w_proj_t, b_proj_t, out, M_ROWS, 1152, 1152,
                                           out, ss + 2 * C_DIM);

    // 10) cross attention
    sgemm_kernel<0><<<dim3(9, 128), 256>>>(out, wq_c, bq_c, xm, M_ROWS, 1152, 1152, nullptr, nullptr);
    sgemm_kernel<0><<<dim3(18, 4), 256>>>(y_in, wkv_c, bkv_c, kvc, 480, 2304, 1152, nullptr, nullptr);
    flash_attn_kernel<30><<<dim3(16, 16, 4), 256, CRS_SMEM>>>(
        xm, kvc, kvc + 1152, attn, 1152, 2304, 1152, 4096, 120, 120);
    // x = x + (attn @ wo_c + b)
    sgemm_kernel<2><<<dim3(9, 128), 256>>>(attn, wo_c, bo_c, out, M_ROWS, 1152, 1152, out, nullptr);

    // 11) MLP
    ln_mod_kernel<<<M_ROWS, 256>>>(out, xm, ss, 3, 4);
    sgemm_kernel<3><<<dim3(36, 128), 256>>>(xm, w_fc1, b_fc1, big, M_ROWS, 4608, 1152, nullptr, nullptr);
    sgemm_kernel<1><<<dim3(9, 128), 256>>>(big, w_fc2, b_fc2, out, M_ROWS, 1152, 4608,
                                           out, ss + 5 * C_DIM);
}

// round 3
// speedup vs baseline: 3.1553x; 3.1553x over previous
#include <cuda_runtime.h>
#include <cuda_fp16.h>
#include <math.h>
#include <stdint.h>

// ---------------- problem constants ----------------
#define C_DIM   1152
#define NHEADS  16
#define HD      72
#define B_SZ    4
#define T_SZ    16
#define S_SZ    256
#define N_TOK   4096
#define M_ROWS  16384
#define SS_STRIDE 6912
#define SCALE_ATTN 0.11785113019775792f

// ---------------- ptx helpers (sm_80-level only; target is plain compute_103) ----------------
__device__ __forceinline__ uint32_t smem_to_u32(const void* p) {
    uint32_t a;
    asm("{ .reg .u64 t; cvta.to.shared.u64 t, %1; cvt.u32.u64 %0, t; }" : "=r"(a) : "l"(p));
    return a;
}
__device__ __forceinline__ void cp16(uint32_t saddr, const void* gaddr) {
    asm volatile("cp.async.cg.shared.global [%0], [%1], 16;" :: "r"(saddr), "l"(gaddr));
}
#define CP_COMMIT() asm volatile("cp.async.commit_group;" ::: "memory")
#define CP_WAIT(n)  asm volatile("cp.async.wait_group %0;" :: "n"(n) : "memory")

__device__ __forceinline__ void ldsm_x4(uint32_t* r, uint32_t addr) {
    asm volatile("ldmatrix.sync.aligned.m8n8.x4.shared.b16 {%0,%1,%2,%3}, [%4];"
        : "=r"(r[0]), "=r"(r[1]), "=r"(r[2]), "=r"(r[3]) : "r"(addr));
}
__device__ __forceinline__ void mma16816(float* c, const uint32_t* a, uint32_t b0, uint32_t b1) {
    asm volatile("mma.sync.aligned.m16n8k16.row.col.f32.f16.f16.f32 "
        "{%0,%1,%2,%3}, {%4,%5,%6,%7}, {%8,%9}, {%0,%1,%2,%3};"
        : "+f"(c[0]), "+f"(c[1]), "+f"(c[2]), "+f"(c[3])
        : "r"(a[0]), "r"(a[1]), "r"(a[2]), "r"(a[3]), "r"(b0), "r"(b1));
}

// ---------------- scratch (device globals) ----------------
__device__ __align__(16) __half g_wt_qkv_s[3456 * 1152];
__device__ __align__(16) __half g_wt_proj_s[1152 * 1152];
__device__ __align__(16) __half g_wt_qkv_t[3456 * 1152];
__device__ __align__(16) __half g_wt_proj_t[1152 * 1152];
__device__ __align__(16) __half g_wt_q_c [1152 * 1152];
__device__ __align__(16) __half g_wt_kv_c[2304 * 1152];
__device__ __align__(16) __half g_wt_wo_c[1152 * 1152];
__device__ __align__(16) __half g_wt_fc1 [4608 * 1152];
__device__ __align__(16) __half g_wt_fc2 [1152 * 4608];
__device__ __align__(16) __half g_xm  [(size_t)M_ROWS * 1152];
__device__ __align__(16) __half g_xh  [(size_t)M_ROWS * 1152];
__device__ __align__(16) __half g_big [(size_t)M_ROWS * 4608];
__device__ __align__(16) __half g_attn[(size_t)M_ROWS * 1152];
__device__ __align__(16) __half g_kvc [512 * 2304];
__device__ __align__(16) __half g_yh  [480 * 1152];
__device__ float  g_ss  [B_SZ * SS_STRIDE];

// ---------------- weight transpose+convert: w[K,N] fp32 -> wt[N,K] f16 ----------------
__global__ void transpose_f2h_kernel(const float* __restrict__ w, __half* __restrict__ wt,
                                     int K, int N)
{
    __shared__ float tile[32][33];
    int n0 = blockIdx.x * 32, k0 = blockIdx.y * 32;
    int tx = threadIdx.x, ty = threadIdx.y;
    #pragma unroll
    for (int i = 0; i < 32; i += 8)
        tile[ty + i][tx] = w[(size_t)(k0 + ty + i) * N + n0 + tx];
    __syncthreads();
    #pragma unroll
    for (int i = 0; i < 32; i += 8)
        wt[(size_t)(n0 + ty + i) * K + k0 + tx] = __float2half(tile[tx][ty + i]);
}

__global__ void f2h_kernel(const float* __restrict__ in, __half* __restrict__ out, int n)
{
    int i = blockIdx.x * blockDim.x + threadIdx.x;
    if (i < n) out[i] = __float2half(in[i]);
}

// ---------------- ss = table + t ----------------
__global__ void compute_ss_kernel(const float* __restrict__ t, const float* __restrict__ table,
                                  float* __restrict__ ss)
{
    int idx = blockIdx.x * blockDim.x + threadIdx.x;
    if (idx >= B_SZ * SS_STRIDE) return;
    int b = idx / SS_STRIDE;
    ss[idx] = table[idx - b * SS_STRIDE] + t[idx];
}

// ---------------- layernorm + modulate -> f16 ----------------
__global__ void ln_mod_kernel(const float* __restrict__ X, __half* __restrict__ Y,
                              const float* __restrict__ ss, int shift_idx, int scale_idx)
{
    int row = blockIdx.x;
    int b = row >> 12;
    const float* xp = X + (size_t)row * C_DIM;
    float lsum = 0.f, lsq = 0.f;
    for (int i = threadIdx.x; i < C_DIM; i += 256) {
        float v = xp[i];
        lsum += v; lsq += v * v;
    }
    __shared__ float s_sum[8], s_sq[8];
    int lane = threadIdx.x & 31, warp = threadIdx.x >> 5;
    #pragma unroll
    for (int off = 16; off > 0; off >>= 1) {
        lsum += __shfl_down_sync(0xffffffffu, lsum, off);
        lsq  += __shfl_down_sync(0xffffffffu, lsq,  off);
    }
    if (lane == 0) { s_sum[warp] = lsum; s_sq[warp] = lsq; }
    __syncthreads();
    __shared__ float s_mu, s_rstd;
    if (threadIdx.x == 0) {
        float su = 0.f, sq = 0.f;
        #pragma unroll
        for (int w = 0; w < 8; w++) { su += s_sum[w]; sq += s_sq[w]; }
        float mu = su / (float)C_DIM;
        float var = sq / (float)C_DIM - mu * mu;
        s_mu = mu; s_rstd = rsqrtf(var + 1e-6f);
    }
    __syncthreads();
    float mu = s_mu, rstd = s_rstd;
    const float* sh = ss + (size_t)(b * 6 + shift_idx) * C_DIM;
    const float* sc = ss + (size_t)(b * 6 + scale_idx) * C_DIM;
    __half* yp = Y + (size_t)row * C_DIM;
    for (int i = threadIdx.x; i < C_DIM; i += 256) {
        float v = (xp[i] - mu) * rstd;
        yp[i] = __float2half(v * (1.f + sc[i]) + sh[i]);
    }
}

// ---------------- f16 tensor-core GEMM: Out = A[M,K] @ Wt[N,K]^T + bias ----------------
// 128x128 tile, BK=32, cp.async double buffer, mma.sync.m16n8k16.
// EPI 0: OutH = f16(v)
// EPI 1: v = Res + Gate[b,col]*v; Out(fp32)=v; if OutH: OutH=f16(v)
// EPI 2: v = Res + v; Out(fp32)=v
// EPI 3: OutH = f16(gelu_tanh(v))
template<int EPI>
__global__ __launch_bounds__(256)
void hgemm_kernel(const __half* __restrict__ A, const __half* __restrict__ Wt,
                  const float* __restrict__ bias,
                  float* __restrict__ Out, __half* __restrict__ OutH,
                  int M, int N, int K,
                  const float* __restrict__ Res, const float* __restrict__ Gate)
{
    __shared__ __align__(16) __half As[2][128 * 32];
    __shared__ __align__(16) __half Bs[2][128 * 32];
    int tid = threadIdx.x;
    int bm = blockIdx.y * 128;
    int bn = blockIdx.x * 128;
    int warp = tid >> 5, lane = tid & 31;
    int wm = warp & 1, wn = warp >> 1;   // warp -> (64-row group, 32-col group)

    uint32_t aB = smem_to_u32(As);
    uint32_t bB = smem_to_u32(Bs);

    // per-thread load mapping: row = tid/2, two 16B chunks at c0=(tid&1)*2
    int lrow = tid >> 1;
    int lc0 = (tid & 1) * 2;
    int agr = min(bm + lrow, M - 1);
    const __half* agp = A  + (size_t)agr * K + lc0 * 8;
    const __half* bgp = Wt + (size_t)(bn + lrow) * K + lc0 * 8;
    uint32_t asw0 = (uint32_t)(lrow * 64 + (((lc0)     ^ (lrow & 3)) << 4));
    uint32_t asw1 = (uint32_t)(lrow * 64 + (((lc0 + 1) ^ (lrow & 3)) << 4));

    int numK = K >> 5;

    // prologue: tile 0 -> buf 0
    cp16(aB + asw0, agp);     cp16(aB + asw1, agp + 8);
    cp16(bB + asw0, bgp);     cp16(bB + asw1, bgp + 8);
    CP_COMMIT();

    float acc[4][4][4];
    #pragma unroll
    for (int i = 0; i < 4; i++)
        #pragma unroll
        for (int j = 0; j < 4; j++)
            #pragma unroll
            for (int k = 0; k < 4; k++) acc[i][j][k] = 0.f;

    for (int kt = 0; kt < numK; kt++) {
        if (kt + 1 < numK) {
            int nb = (kt + 1) & 1;
            int koff = (kt + 1) * 32;
            uint32_t ab2 = aB + nb * 8192, bb2 = bB + nb * 8192;
            cp16(ab2 + asw0, agp + koff);     cp16(ab2 + asw1, agp + koff + 8);
            cp16(bb2 + asw0, bgp + koff);     cp16(bb2 + asw1, bgp + koff + 8);
            CP_COMMIT();
            CP_WAIT(1);
        } else {
            CP_WAIT(0);
        }
        __syncthreads();

        uint32_t ab = aB + (kt & 1) * 8192;
        uint32_t bb = bB + (kt & 1) * 8192;
        #pragma unroll
        for (int kk = 0; kk < 2; kk++) {
            uint32_t a[4][4];
            #pragma unroll
            for (int mt = 0; mt < 4; mt++) {
                int row = wm * 64 + mt * 16 + (lane & 15);
                int c = kk * 2 + (lane >> 4);
                ldsm_x4(a[mt], ab + row * 64 + ((c ^ (row & 3)) << 4));
            }
            uint32_t b[2][4];
            #pragma unroll
            for (int p = 0; p < 2; p++) {
                int row = wn * 32 + p * 16 + ((lane >> 4) << 3) + (lane & 7);
                int c = kk * 2 + ((lane >> 3) & 1);
                ldsm_x4(b[p], bb + row * 64 + ((c ^ (row & 3)) << 4));
            }
            #pragma unroll
            for (int mt = 0; mt < 4; mt++)
                #pragma unroll
                for (int nt = 0; nt < 4; nt++)
                    mma16816(acc[mt][nt], a[mt], b[nt >> 1][(nt & 1) * 2], b[nt >> 1][(nt & 1) * 2 + 1]);
        }
        __syncthreads();
    }

    // epilogue
    bool hasH = (OutH != nullptr);
    #pragma unroll
    for (int mt = 0; mt < 4; mt++) {
        #pragma unroll
        for (int i = 0; i < 2; i++) {
            int row = bm + wm * 64 + mt * 16 + (lane >> 2) + i * 8;
            if (row >= M) continue;
            size_t orow = (size_t)row * N;
            int b6 = (row >> 12) * SS_STRIDE;
            #pragma unroll
            for (int nt = 0; nt < 4; nt++) {
                int col = bn + wn * 32 + nt * 8 + ((lane & 3) << 1);
                float v0 = acc[mt][nt][i * 2]     + bias[col];
                float v1 = acc[mt][nt][i * 2 + 1] + bias[col + 1];
                size_t o = orow + col;
                if (EPI == 0) {
                    *(__half2*)(OutH + o) = __floats2half2_rn(v0, v1);
                } else if (EPI == 1) {
                    v0 = Res[o]     + Gate[b6 + col]     * v0;
                    v1 = Res[o + 1] + Gate[b6 + col + 1] * v1;
                    *(float2*)(Out + o) = make_float2(v0, v1);
                    if (hasH) *(__half2*)(OutH + o) = __floats2half2_rn(v0, v1);
                } else if (EPI == 2) {
                    v0 += Res[o]; v1 += Res[o + 1];
                    *(float2*)(Out + o) = make_float2(v0, v1);
                } else {
                    float t0 = v0 + 0.044715f * v0 * v0 * v0;
                    float t1 = v1 + 0.044715f * v1 * v1 * v1;
                    float gg0 = 0.5f * v0 * (1.f + tanhf(0.79788456080286536f * t0));
                    float gg1 = 0.5f * v1 * (1.f + tanhf(0.79788456080286536f * t1));
                    *(__half2*)(OutH + o) = __floats2half2_rn(gg0, gg1);
                }
            }
        }
    }
}

// ---------------- flash attention (non-causal), f16 I/O ----------------
template<int KTILE>
__global__ __launch_bounds__(256, 1)
void flash_attn_kernel(const __half* __restrict__ Qp, const __half* __restrict__ Kp,
                       const __half* __restrict__ Vp, __half* __restrict__ Op,
                       int q_ld, int kv_ld, int o_ld,
                       int q_unit_stride, int kv_unit_stride, int kv_len)
{
    extern __shared__ float sm[];
    float* q_s = sm;
    float* k_s = sm + 256 * 73;
    float* v_s = k_s + KTILE * 73;

    int u = blockIdx.z, h = blockIdx.y, qt = blockIdx.x;
    size_t qrow0 = (size_t)u * q_unit_stride + (size_t)qt * 256;
    size_t kvrow0 = (size_t)u * kv_unit_stride;
    int hc = h * HD;
    int tid = threadIdx.x;

    for (int idx = tid; idx < 256 * HD; idx += 256) {
        int i = idx / HD, d = idx - i * HD;
        q_s[i * 73 + d] = __half2float(Qp[(qrow0 + i) * q_ld + hc + d]);
    }
    __syncthreads();

    float o[HD];
    #pragma unroll
    for (int d = 0; d < HD; d++) o[d] = 0.f;
    float m = -1e30f, l = 0.f;

    for (int j0 = 0; j0 < kv_len; j0 += KTILE) {
        for (int idx = tid; idx < KTILE * HD; idx += 256) {
            int j = idx / HD, d = idx - j * HD;
            size_t rr = (kvrow0 + j0 + j) * (size_t)kv_ld + hc + d;
            k_s[j * 73 + d] = __half2float(Kp[rr]);
            v_s[j * 73 + d] = __half2float(Vp[rr]);
        }
        __syncthreads();

        float s[KTILE];
        #pragma unroll
        for (int j = 0; j < KTILE; j++) s[j] = 0.f;
        #pragma unroll 2
        for (int d = 0; d < HD; d++) {
            float qd = q_s[tid * 73 + d];
            #pragma unroll
            for (int j = 0; j < KTILE; j++)
                s[j] += qd * k_s[j * 73 + d];
        }
        float mt = m;
        #pragma unroll
        for (int j = 0; j < KTILE; j++) { s[j] *= SCALE_ATTN; mt = fmaxf(mt, s[j]); }
        float corr = __expf(m - mt);
        l *= corr;
        #pragma unroll
        for (int d = 0; d < HD; d++) o[d] *= corr;
        #pragma unroll
        for (int j = 0; j < KTILE; j++) { float p = __expf(s[j] - mt); l += p; s[j] = p; }
        #pragma unroll 2
        for (int d = 0; d < HD; d++) {
            float a = o[d];
            #pragma unroll
            for (int j = 0; j < KTILE; j++)
                a += s[j] * v_s[j * 73 + d];
            o[d] = a;
        }
        m = mt;
        __syncthreads();
    }

    float inv = 1.f / l;
    __half* op = Op + (qrow0 + tid) * (size_t)o_ld + hc;
    #pragma unroll
    for (int d = 0; d < HD; d++) op[d] = __float2half(o[d] * inv);
}

// ---------------- RoPE in-place on f16 q,k halves ----------------
__global__ void rope_kernel(__half* __restrict__ qkv,
                            const float* __restrict__ cosb, const float* __restrict__ sinb)
{
    int idx = blockIdx.x * blockDim.x + threadIdx.x;
    if (idx >= M_ROWS * NHEADS * 36) return;
    int d2 = idx % 36;
    int h  = (idx / 36) % NHEADS;
    int r  = idx / (36 * NHEADS);
    int t  = (r >> 8) & 15;
    float c = cosb[t * 36 + d2];
    float s = sinb[t * 36 + d2];
    size_t base = (size_t)r * 3456 + h * HD + 2 * d2;
    __half2 q = *(__half2*)(qkv + base);
    float qe = __low2float(q), qo = __high2float(q);
    *(__half2*)(qkv + base) = __floats2half2_rn(qe * c - qo * s, qe * s + qo * c);
    __half2 k = *(__half2*)(qkv + base + 1152);
    float ke = __low2float(k), ko = __high2float(k);
    *(__half2*)(qkv + base + 1152) = __floats2half2_rn(ke * c - ko * s, ke * s + ko * c);
}

// ---------------- temporal causal attention, f16 I/O ----------------
__global__ void temporal_attn_kernel(const __half* __restrict__ qkv, __half* __restrict__ O)
{
    int idx = blockIdx.x * blockDim.x + threadIdx.x;
    int tq = idx & 15;
    int h  = (idx >> 4) & 15;
    int s  = (idx >> 8) & 255;
    int b  = idx >> 16;
    size_t rowq = (size_t)b * N_TOK + (size_t)tq * 256 + s;
    const __half* qp = qkv + rowq * 3456 + h * HD;
    float q[HD];
    #pragma unroll
    for (int d = 0; d < HD; d++) q[d] = __half2float(qp[d]);

    float sc[T_SZ];
    float m = -1e30f;
    #pragma unroll
    for (int tk = 0; tk < T_SZ; tk++) {
        const __half* kp = qkv + ((size_t)b * N_TOK + (size_t)tk * 256 + s) * 3456 + 1152 + h * HD;
        float a = 0.f;
        #pragma unroll
        for (int d = 0; d < HD; d++) a += q[d] * __half2float(kp[d]);
        a *= SCALE_ATTN;
        if (tk > tq) a = -1e30f;
        sc[tk] = a;
        m = fmaxf(m, a);
    }
    float l = 0.f;
    #pragma unroll
    for (int tk = 0; tk < T_SZ; tk++) { sc[tk] = __expf(sc[tk] - m); l += sc[tk]; }
    float inv = 1.f / l;

    __half* op = O + rowq * C_DIM + h * HD;
    #pragma unroll 2
    for (int d = 0; d < HD; d++) {
        float a = 0.f;
        #pragma unroll
        for (int tk = 0; tk < T_SZ; tk++)
            a += sc[tk] * __half2float(qkv[((size_t)b * N_TOK + (size_t)tk * 256 + s) * 3456 + 2304 + h * HD + d]);
        op[d] = __float2half(a * inv);
    }
}

// ---------------- host orchestration ----------------
extern "C" void kernel_launch(void* const* d_in, const int* in_sizes, int n_in,
                              void* d_out, int out_size)
{
    (void)in_sizes; (void)n_in; (void)out_size;
    const float* x_in    = (const float*)d_in[0];
    const float* y_in    = (const float*)d_in[1];
    const float* t_in    = (const float*)d_in[2];
    const float* sstab   = (const float*)d_in[3];
    const float* w_qkv_s = (const float*)d_in[4];
    const float* b_qkv_s = (const float*)d_in[5];
    const float* w_proj_s = (const float*)d_in[6];
    const float* b_proj_s = (const float*)d_in[7];
    const float* w_qkv_t = (const float*)d_in[8];
    const float* b_qkv_t = (const float*)d_in[9];
    const float* w_proj_t = (const float*)d_in[10];
    const float* b_proj_t = (const float*)d_in[11];
    const float* wq_c  = (const float*)d_in[12];
    const float* bq_c  = (const float*)d_in[13];
    const float* wkv_c = (const float*)d_in[14];
    const float* bkv_c = (const float*)d_in[15];
    const float* wo_c  = (const float*)d_in[16];
    const float* bo_c  = (const float*)d_in[17];
    const float* w_fc1 = (const float*)d_in[18];
    const float* b_fc1 = (const float*)d_in[19];
    const float* w_fc2 = (const float*)d_in[20];
    const float* b_fc2 = (const float*)d_in[21];
    const float* f_cos = (const float*)d_in[22];
    const float* f_sin = (const float*)d_in[23];
    float* out = (float*)d_out;

    float* ss;   cudaGetSymbolAddress((void**)&ss, g_ss);
    __half *wt_qkv_s, *wt_proj_s, *wt_qkv_t, *wt_proj_t, *wt_q_c, *wt_kv_c, *wt_wo_c, *wt_fc1, *wt_fc2;
    __half *xm, *xh, *big, *attn, *kvc, *yh;
    cudaGetSymbolAddress((void**)&wt_qkv_s, g_wt_qkv_s);
    cudaGetSymbolAddress((void**)&wt_proj_s, g_wt_proj_s);
    cudaGetSymbolAddress((void**)&wt_qkv_t, g_wt_qkv_t);
    cudaGetSymbolAddress((void**)&wt_proj_t, g_wt_proj_t);
    cudaGetSymbolAddress((void**)&wt_q_c,  g_wt_q_c);
    cudaGetSymbolAddress((void**)&wt_kv_c, g_wt_kv_c);
    cudaGetSymbolAddress((void**)&wt_wo_c, g_wt_wo_c);
    cudaGetSymbolAddress((void**)&wt_fc1,  g_wt_fc1);
    cudaGetSymbolAddress((void**)&wt_fc2,  g_wt_fc2);
    cudaGetSymbolAddress((void**)&xm,   g_xm);
    cudaGetSymbolAddress((void**)&xh,   g_xh);
    cudaGetSymbolAddress((void**)&big,  g_big);
    cudaGetSymbolAddress((void**)&attn, g_attn);
    cudaGetSymbolAddress((void**)&kvc,  g_kvc);
    cudaGetSymbolAddress((void**)&yh,   g_yh);

    const int SPA_SMEM = (256 * 73 + 2 * 32 * 73) * 4;
    const int CRS_SMEM = (256 * 73 + 2 * 30 * 73) * 4;
    cudaFuncSetAttribute(flash_attn_kernel<32>, cudaFuncAttributeMaxDynamicSharedMemorySize, SPA_SMEM);
    cudaFuncSetAttribute(flash_attn_kernel<30>, cudaFuncAttributeMaxDynamicSharedMemorySize, CRS_SMEM);

    dim3 tb(32, 8);
    // weight transposes (fp32 -> f16, [K,N] -> [N,K])
    transpose_f2h_kernel<<<dim3(3456 / 32, 1152 / 32), tb>>>(w_qkv_s, wt_qkv_s, 1152, 3456);
    transpose_f2h_kernel<<<dim3(1152 / 32, 1152 / 32), tb>>>(w_proj_s, wt_proj_s, 1152, 1152);
    transpose_f2h_kernel<<<dim3(3456 / 32, 1152 / 32), tb>>>(w_qkv_t, wt_qkv_t, 1152, 3456);
    transpose_f2h_kernel<<<dim3(1152 / 32, 1152 / 32), tb>>>(w_proj_t, wt_proj_t, 1152, 1152);
    transpose_f2h_kernel<<<dim3(1152 / 32, 1152 / 32), tb>>>(wq_c, wt_q_c, 1152, 1152);
    transpose_f2h_kernel<<<dim3(2304 / 32, 1152 / 32), tb>>>(wkv_c, wt_kv_c, 1152, 2304);
    transpose_f2h_kernel<<<dim3(1152 / 32, 1152 / 32), tb>>>(wo_c, wt_wo_c, 1152, 1152);
    transpose_f2h_kernel<<<dim3(4608 / 32, 1152 / 32), tb>>>(w_fc1, wt_fc1, 1152, 4608);
    transpose_f2h_kernel<<<dim3(1152 / 32, 4608 / 32), tb>>>(w_fc2, wt_fc2, 4608, 1152);
    f2h_kernel<<<(480 * 1152 + 255) / 256, 256>>>(y_in, yh, 480 * 1152);

    compute_ss_kernel<<<(B_SZ * SS_STRIDE + 255) / 256, 256>>>(t_in, sstab, ss);
    ln_mod_kernel<<<M_ROWS, 256>>>(x_in, xm, ss, 0, 1);

    // spatial branch
    hgemm_kernel<0><<<dim3(27, 128), 256>>>(xm, wt_qkv_s, b_qkv_s,
        nullptr, big, M_ROWS, 3456, 1152, nullptr, nullptr);
    flash_attn_kernel<32><<<dim3(1, 16, 64), 256, SPA_SMEM>>>(
        big, big + 1152, big + 2304, attn, 3456, 3456, 1152, 256, 256, 256);
    hgemm_kernel<1><<<dim3(9, 128), 256>>>(attn, wt_proj_s, b_proj_s,
        out, xh, M_ROWS, 1152, 1152, x_in, ss + 2 * C_DIM);

    // temporal branch
    hgemm_kernel<0><<<dim3(27, 128), 256>>>(xh, wt_qkv_t, b_qkv_t,
        nullptr, big, M_ROWS, 3456, 1152, nullptr, nullptr);
    rope_kernel<<<(M_ROWS * NHEADS * 36 + 255) / 256, 256>>>(big, f_cos, f_sin);
    temporal_attn_kernel<<<1024, 256>>>(big, attn);
    hgemm_kernel<1><<<dim3(9, 128), 256>>>(attn, wt_proj_t, b_proj_t,
        out, xh, M_ROWS, 1152, 1152, out, ss + 2 * C_DIM);

    // cross attention
    hgemm_kernel<0><<<dim3(9, 128), 256>>>(xh, wt_q_c, bq_c,
        nullptr, xm, M_ROWS, 1152, 1152, nullptr, nullptr);
    hgemm_kernel<0><<<dim3(18, 4), 256>>>(yh, wt_kv_c, bkv_c,
        nullptr, kvc, 480, 2304, 1152, nullptr, nullptr);
    flash_attn_kernel<30><<<dim3(16, 16, 4), 256, CRS_SMEM>>>(
        xm, kvc, kvc + 1152, attn, 1152, 2304, 1152, 4096, 120, 120);
    hgemm_kernel<2><<<dim3(9, 128), 256>>>(attn, wt_wo_c, bo_c,
        out, nullptr, M_ROWS, 1152, 1152, out, nullptr);

    // MLP
    ln_mod_kernel<<<M_ROWS, 256>>>(out, xm, ss, 3, 4);
    hgemm_kernel<3><<<dim3(36, 128), 256>>>(xm, wt_fc1, b_fc1,
        nullptr, big, M_ROWS, 4608, 1152, nullptr, nullptr);
    hgemm_kernel<1><<<dim3(9, 128), 256>>>(big, wt_fc2, b_fc2,
        out, nullptr, M_ROWS, 1152, 4608, out, ss + 5 * C_DIM);
}

// round 4
// speedup vs baseline: 4.6500x; 1.4737x over previous
#include <cuda_runtime.h>
#include <cuda_fp16.h>
#include <math.h>
#include <stdint.h>

// ---------------- problem constants ----------------
#define C_DIM   1152
#define NHEADS  16
#define HD      72
#define B_SZ    4
#define T_SZ    16
#define S_SZ    256
#define N_TOK   4096
#define M_ROWS  16384
#define SS_STRIDE 6912
#define SCALE_ATTN 0.11785113019775792f

// ---------------- ptx helpers (sm_80-level; harness targets plain compute_103) ----------------
__device__ __forceinline__ uint32_t smem_to_u32(const void* p) {
    uint32_t a;
    asm("{ .reg .u64 t; cvta.to.shared.u64 t, %1; cvt.u32.u64 %0, t; }" : "=r"(a) : "l"(p));
    return a;
}
__device__ __forceinline__ void cp16(uint32_t saddr, const void* gaddr) {
    asm volatile("cp.async.cg.shared.global [%0], [%1], 16;" :: "r"(saddr), "l"(gaddr));
}
#define CP_COMMIT() asm volatile("cp.async.commit_group;" ::: "memory")
#define CP_WAIT(n)  asm volatile("cp.async.wait_group %0;" :: "n"(n) : "memory")

__device__ __forceinline__ void ldsm_x4(uint32_t* r, uint32_t addr) {
    asm volatile("ldmatrix.sync.aligned.m8n8.x4.shared.b16 {%0,%1,%2,%3}, [%4];"
        : "=r"(r[0]), "=r"(r[1]), "=r"(r[2]), "=r"(r[3]) : "r"(addr));
}
__device__ __forceinline__ void mma16816(float* c, const uint32_t* a, uint32_t b0, uint32_t b1) {
    asm volatile("mma.sync.aligned.m16n8k16.row.col.f32.f16.f16.f32 "
        "{%0,%1,%2,%3}, {%4,%5,%6,%7}, {%8,%9}, {%0,%1,%2,%3};"
        : "+f"(c[0]), "+f"(c[1]), "+f"(c[2]), "+f"(c[3])
        : "r"(a[0]), "r"(a[1]), "r"(a[2]), "r"(a[3]), "r"(b0), "r"(b1));
}

// ---------------- scratch (device globals) ----------------
__device__ __align__(16) __half g_wt_qkv_s[3456 * 1152];
__device__ __align__(16) __half g_wt_proj_s[1152 * 1152];
__device__ __align__(16) __half g_wt_qkv_t[3456 * 1152];
__device__ __align__(16) __half g_wt_proj_t[1152 * 1152];
__device__ __align__(16) __half g_wt_q_c [1152 * 1152];
__device__ __align__(16) __half g_wt_kv_c[2304 * 1152];
__device__ __align__(16) __half g_wt_wo_c[1152 * 1152];
__device__ __align__(16) __half g_wt_fc1 [4608 * 1152];
__device__ __align__(16) __half g_wt_fc2 [1152 * 4608];
__device__ __align__(16) __half g_xm  [(size_t)M_ROWS * 1152];
__device__ __align__(16) __half g_xh  [(size_t)M_ROWS * 1152];
__device__ __align__(16) __half g_big [(size_t)M_ROWS * 4608];
__device__ __align__(16) __half g_attn[(size_t)M_ROWS * 1152];
__device__ __align__(16) __half g_kvc [512 * 2304];
__device__ __align__(16) __half g_yh  [480 * 1152];
__device__ float  g_ss  [B_SZ * SS_STRIDE];

// ---------------- weight transpose+convert: w[K,N] fp32 -> wt[N,K] f16 ----------------
__global__ void transpose_f2h_kernel(const float* __restrict__ w, __half* __restrict__ wt,
                                     int K, int N)
{
    __shared__ float tile[32][33];
    int n0 = blockIdx.x * 32, k0 = blockIdx.y * 32;
    int tx = threadIdx.x, ty = threadIdx.y;
    #pragma unroll
    for (int i = 0; i < 32; i += 8)
        tile[ty + i][tx] = w[(size_t)(k0 + ty + i) * N + n0 + tx];
    __syncthreads();
    #pragma unroll
    for (int i = 0; i < 32; i += 8)
        wt[(size_t)(n0 + ty + i) * K + k0 + tx] = __float2half(tile[tx][ty + i]);
}

__global__ void f2h_kernel(const float* __restrict__ in, __half* __restrict__ out, int n)
{
    int i = blockIdx.x * blockDim.x + threadIdx.x;
    if (i < n) out[i] = __float2half(in[i]);
}

// ---------------- ss = table + t ----------------
__global__ void compute_ss_kernel(const float* __restrict__ t, const float* __restrict__ table,
                                  float* __restrict__ ss)
{
    int idx = blockIdx.x * blockDim.x + threadIdx.x;
    if (idx >= B_SZ * SS_STRIDE) return;
    int b = idx / SS_STRIDE;
    ss[idx] = table[idx - b * SS_STRIDE] + t[idx];
}

// ---------------- layernorm + modulate -> f16 ----------------
__global__ void ln_mod_kernel(const float* __restrict__ X, __half* __restrict__ Y,
                              const float* __restrict__ ss, int shift_idx, int scale_idx)
{
    int row = blockIdx.x;
    int b = row >> 12;
    const float* xp = X + (size_t)row * C_DIM;
    float lsum = 0.f, lsq = 0.f;
    for (int i = threadIdx.x; i < C_DIM; i += 256) {
        float v = xp[i];
        lsum += v; lsq += v * v;
    }
    __shared__ float s_sum[8], s_sq[8];
    int lane = threadIdx.x & 31, warp = threadIdx.x >> 5;
    #pragma unroll
    for (int off = 16; off > 0; off >>= 1) {
        lsum += __shfl_down_sync(0xffffffffu, lsum, off);
        lsq  += __shfl_down_sync(0xffffffffu, lsq,  off);
    }
    if (lane == 0) { s_sum[warp] = lsum; s_sq[warp] = lsq; }
    __syncthreads();
    __shared__ float s_mu, s_rstd;
    if (threadIdx.x == 0) {
        float su = 0.f, sq = 0.f;
        #pragma unroll
        for (int w = 0; w < 8; w++) { su += s_sum[w]; sq += s_sq[w]; }
        float mu = su / (float)C_DIM;
        float var = sq / (float)C_DIM - mu * mu;
        s_mu = mu; s_rstd = rsqrtf(var + 1e-6f);
    }
    __syncthreads();
    float mu = s_mu, rstd = s_rstd;
    const float* sh = ss + (size_t)(b * 6 + shift_idx) * C_DIM;
    const float* sc = ss + (size_t)(b * 6 + scale_idx) * C_DIM;
    __half* yp = Y + (size_t)row * C_DIM;
    for (int i = threadIdx.x; i < C_DIM; i += 256) {
        float v = (xp[i] - mu) * rstd;
        yp[i] = __float2half(v * (1.f + sc[i]) + sh[i]);
    }
}

// ---------------- f16 tensor-core GEMM, 3-stage cp.async pipeline ----------------
// Out = A[M,K] @ Wt[N,K]^T + bias ; 128x128 tile, BK=32.
// EPI 0: OutH = f16(v)
// EPI 1: v = Res + Gate[b,col]*v; Out(fp32)=v; if OutH: OutH=f16(v)
// EPI 2: v = Res + v; Out(fp32)=v
// EPI 3: OutH = f16(gelu_tanh(v))
template<int EPI>
__global__ __launch_bounds__(256, 2)
void hgemm_kernel(const __half* __restrict__ A, const __half* __restrict__ Wt,
                  const float* __restrict__ bias,
                  float* __restrict__ Out, __half* __restrict__ OutH,
                  int M, int N, int K,
                  const float* __restrict__ Res, const float* __restrict__ Gate)
{
    extern __shared__ char gsm[];   // [3][128*32] A halves + [3][128*32] B halves
    int tid = threadIdx.x;
    int bm = blockIdx.y * 128;
    int bn = blockIdx.x * 128;
    int warp = tid >> 5, lane = tid & 31;
    int wm = warp & 1, wn = warp >> 1;

    uint32_t aB = smem_to_u32(gsm);
    uint32_t bB = aB + 24576;

    int lrow = tid >> 1;
    int lc0 = (tid & 1) * 2;
    int agr = min(bm + lrow, M - 1);
    const __half* agp = A  + (size_t)agr * K + lc0 * 8;
    const __half* bgp = Wt + (size_t)(bn + lrow) * K + lc0 * 8;
    uint32_t asw0 = (uint32_t)(lrow * 64 + (((lc0)     ^ (lrow & 3)) << 4));
    uint32_t asw1 = (uint32_t)(lrow * 64 + (((lc0 + 1) ^ (lrow & 3)) << 4));

    int numK = K >> 5;

    // prologue: stages 0,1
    cp16(aB + asw0, agp);      cp16(aB + asw1, agp + 8);
    cp16(bB + asw0, bgp);      cp16(bB + asw1, bgp + 8);
    CP_COMMIT();
    cp16(aB + 8192 + asw0, agp + 32);  cp16(aB + 8192 + asw1, agp + 40);
    cp16(bB + 8192 + asw0, bgp + 32);  cp16(bB + 8192 + asw1, bgp + 40);
    CP_COMMIT();

    float acc[4][4][4];
    #pragma unroll
    for (int i = 0; i < 4; i++)
        #pragma unroll
        for (int j = 0; j < 4; j++)
            #pragma unroll
            for (int k = 0; k < 4; k++) acc[i][j][k] = 0.f;

    for (int kt = 0; kt < numK; kt++) {
        CP_WAIT(1);
        __syncthreads();
        if (kt + 2 < numK) {
            int nb = kt + 2; nb -= (nb / 3) * 3;
            int koff = (kt + 2) * 32;
            uint32_t ab2 = aB + nb * 8192, bb2 = bB + nb * 8192;
            cp16(ab2 + asw0, agp + koff);  cp16(ab2 + asw1, agp + koff + 8);
            cp16(bb2 + asw0, bgp + koff);  cp16(bb2 + asw1, bgp + koff + 8);
        }
        CP_COMMIT();

        int cb = kt; cb -= (cb / 3) * 3;
        uint32_t ab = aB + cb * 8192;
        uint32_t bb = bB + cb * 8192;
        #pragma unroll
        for (int kk = 0; kk < 2; kk++) {
            uint32_t a[4][4];
            #pragma unroll
            for (int mt = 0; mt < 4; mt++) {
                int row = wm * 64 + mt * 16 + (lane & 15);
                int c = kk * 2 + (lane >> 4);
                ldsm_x4(a[mt], ab + row * 64 + ((c ^ (row & 3)) << 4));
            }
            uint32_t b[2][4];
            #pragma unroll
            for (int p = 0; p < 2; p++) {
                int row = wn * 32 + p * 16 + ((lane >> 4) << 3) + (lane & 7);
                int c = kk * 2 + ((lane >> 3) & 1);
                ldsm_x4(b[p], bb + row * 64 + ((c ^ (row & 3)) << 4));
            }
            #pragma unroll
            for (int mt = 0; mt < 4; mt++)
                #pragma unroll
                for (int nt = 0; nt < 4; nt++)
                    mma16816(acc[mt][nt], a[mt], b[nt >> 1][(nt & 1) * 2], b[nt >> 1][(nt & 1) * 2 + 1]);
        }
    }

    // epilogue
    bool hasH = (OutH != nullptr);
    #pragma unroll
    for (int mt = 0; mt < 4; mt++) {
        #pragma unroll
        for (int i = 0; i < 2; i++) {
            int row = bm + wm * 64 + mt * 16 + (lane >> 2) + i * 8;
            if (row >= M) continue;
            size_t orow = (size_t)row * N;
            int b6 = (row >> 12) * SS_STRIDE;
            #pragma unroll
            for (int nt = 0; nt < 4; nt++) {
                int col = bn + wn * 32 + nt * 8 + ((lane & 3) << 1);
                float v0 = acc[mt][nt][i * 2]     + bias[col];
                float v1 = acc[mt][nt][i * 2 + 1] + bias[col + 1];
                size_t o = orow + col;
                if (EPI == 0) {
                    *(__half2*)(OutH + o) = __floats2half2_rn(v0, v1);
                } else if (EPI == 1) {
                    v0 = Res[o]     + Gate[b6 + col]     * v0;
                    v1 = Res[o + 1] + Gate[b6 + col + 1] * v1;
                    *(float2*)(Out + o) = make_float2(v0, v1);
                    if (hasH) *(__half2*)(OutH + o) = __floats2half2_rn(v0, v1);
                } else if (EPI == 2) {
                    v0 += Res[o]; v1 += Res[o + 1];
                    *(float2*)(Out + o) = make_float2(v0, v1);
                } else {
                    float t0 = v0 + 0.044715f * v0 * v0 * v0;
                    float t1 = v1 + 0.044715f * v1 * v1 * v1;
                    float gg0 = 0.5f * v0 * (1.f + tanhf(0.79788456080286536f * t0));
                    float gg1 = 0.5f * v1 * (1.f + tanhf(0.79788456080286536f * t1));
                    *(__half2*)(OutH + o) = __floats2half2_rn(gg0, gg1);
                }
            }
        }
    }
}

// ---------------- mma flash attention (non-causal), f16 I/O ----------------
// Block: 256 q rows x 1 head. KV chunks of 64. 8 warps, each 32 q rows.
// QS[256][88] (padded, k=80 zero-padded), KS[64][88], VT[80][72] (V transposed).
#define MHA_SMEM (256*88*2 + 64*88*2 + 80*72*2)
__global__ __launch_bounds__(256, 1)
void mha_kernel(const __half* __restrict__ Q, const __half* __restrict__ K,
                const __half* __restrict__ V, __half* __restrict__ O,
                int q_ld, int kv_ld, int o_ld,
                int q_us, int kv_us, int kv_len)
{
    extern __shared__ char gsm[];
    __half (*QS)[88] = (__half(*)[88])gsm;
    __half (*KS)[88] = (__half(*)[88])(gsm + 256 * 88 * 2);
    __half (*VT)[72] = (__half(*)[72])(gsm + 256 * 88 * 2 + 64 * 88 * 2);

    int tid = threadIdx.x, warp = tid >> 5, lane = tid & 31;
    int u = blockIdx.z, h = blockIdx.y, qt = blockIdx.x;
    size_t qrow0 = (size_t)u * q_us + (size_t)qt * 256;
    size_t kvrow0 = (size_t)u * kv_us;
    int hc = h * HD;

    // load Q tile (1 row per thread), zero-pad cols 72..79
    {
        const uint2* src = (const uint2*)(Q + (qrow0 + tid) * q_ld + hc);
        uint2* dst = (uint2*)&QS[tid][0];
        #pragma unroll
        for (int i = 0; i < 18; i++) dst[i] = src[i];
        dst[18] = make_uint2(0, 0);
        dst[19] = make_uint2(0, 0);
    }

    float mrow[2][2] = {{-1e30f, -1e30f}, {-1e30f, -1e30f}};
    float lrow[2][2] = {{0.f, 0.f}, {0.f, 0.f}};
    float o[2][10][4];
    #pragma unroll
    for (int mt = 0; mt < 2; mt++)
        #pragma unroll
        for (int nt = 0; nt < 10; nt++)
            #pragma unroll
            for (int j = 0; j < 4; j++) o[mt][nt][j] = 0.f;

    int nchunk = (kv_len + 63) >> 6;
    for (int jc = 0; jc < nchunk; jc++) {
        int j0 = jc * 64;
        __syncthreads();   // previous chunk's ldsm reads done before overwrite

        // K chunk -> KS[j][d] (zero-pad invalid rows and cols 72..87)
        for (int idx = tid; idx < 64 * 22; idx += 256) {
            int row = idx / 22, c = idx % 22;
            uint2 val = make_uint2(0, 0);
            int gj = j0 + row;
            if (gj < kv_len && c < 18)
                val = *(const uint2*)(K + (kvrow0 + gj) * kv_ld + hc + c * 4);
            *(uint2*)&KS[row][c * 4] = val;
        }
        // V chunk -> VT[d][j] transposed
        for (int idx = tid; idx < 64 * 18; idx += 256) {
            int row = idx / 18, c = idx % 18;
            uint2 val = make_uint2(0, 0);
            int gj = j0 + row;
            if (gj < kv_len)
                val = *(const uint2*)(V + (kvrow0 + gj) * kv_ld + hc + c * 4);
            __half2 v01 = *(__half2*)&val.x;
            __half2 v23 = *(__half2*)&val.y;
            VT[c * 4 + 0][row] = __low2half(v01);
            VT[c * 4 + 1][row] = __high2half(v01);
            VT[c * 4 + 2][row] = __low2half(v23);
            VT[c * 4 + 3][row] = __high2half(v23);
        }
        // zero VT rows 72..79 (padded d)
        for (int idx = tid; idx < 8 * 64; idx += 256) {
            VT[72 + idx / 64][idx % 64] = __float2half(0.f);
        }
        __syncthreads();

        // S = Q @ K^T  (per warp: 32 x 64)
        float s[2][8][4];
        #pragma unroll
        for (int mt = 0; mt < 2; mt++)
            #pragma unroll
            for (int nt = 0; nt < 8; nt++)
                #pragma unroll
                for (int j = 0; j < 4; j++) s[mt][nt][j] = 0.f;

        #pragma unroll
        for (int kt = 0; kt < 5; kt++) {
            uint32_t a[2][4];
            #pragma unroll
            for (int mt = 0; mt < 2; mt++)
                ldsm_x4(a[mt], smem_to_u32(&QS[warp * 32 + mt * 16 + (lane & 15)]
                                             [kt * 16 + (lane >> 4) * 8]));
            uint32_t kb[4][4];
            #pragma unroll
            for (int p = 0; p < 4; p++)
                ldsm_x4(kb[p], smem_to_u32(&KS[p * 16 + ((lane >> 4) << 3) + (lane & 7)]
                                             [kt * 16 + ((lane >> 3) & 1) * 8]));
            #pragma unroll
            for (int mt = 0; mt < 2; mt++)
                #pragma unroll
                for (int nt = 0; nt < 8; nt++)
                    mma16816(s[mt][nt], a[mt], kb[nt >> 1][(nt & 1) * 2], kb[nt >> 1][(nt & 1) * 2 + 1]);
        }

        // online softmax (row stats in 4-lane quads)
        #pragma unroll
        for (int mt = 0; mt < 2; mt++) {
            #pragma unroll
            for (int ih = 0; ih < 2; ih++) {
                float rm = -1e30f;
                #pragma unroll
                for (int nt = 0; nt < 8; nt++) {
                    #pragma unroll
                    for (int jj = 0; jj < 2; jj++) {
                        float v = s[mt][nt][ih * 2 + jj] * SCALE_ATTN;
                        int col = j0 + nt * 8 + (lane & 3) * 2 + jj;
                        if (col >= kv_len) v = -1e30f;
                        s[mt][nt][ih * 2 + jj] = v;
                        rm = fmaxf(rm, v);
                    }
                }
                rm = fmaxf(rm, __shfl_xor_sync(0xffffffffu, rm, 1));
                rm = fmaxf(rm, __shfl_xor_sync(0xffffffffu, rm, 2));
                float mn = fmaxf(mrow[mt][ih], rm);
                float corr = __expf(mrow[mt][ih] - mn);
                mrow[mt][ih] = mn;
                float ls = 0.f;
                #pragma unroll
                for (int nt = 0; nt < 8; nt++) {
                    #pragma unroll
                    for (int jj = 0; jj < 2; jj++) {
                        float p = __expf(s[mt][nt][ih * 2 + jj] - mn);
                        s[mt][nt][ih * 2 + jj] = p;
                        ls += p;
                    }
                }
                ls += __shfl_xor_sync(0xffffffffu, ls, 1);
                ls += __shfl_xor_sync(0xffffffffu, ls, 2);
                lrow[mt][ih] = lrow[mt][ih] * corr + ls;
                #pragma unroll
                for (int nt = 0; nt < 10; nt++) {
                    o[mt][nt][ih * 2]     *= corr;
                    o[mt][nt][ih * 2 + 1] *= corr;
                }
            }
        }

        // O += P @ V   (P: C-frags repacked to A-frags; V from VT)
        #pragma unroll
        for (int kt = 0; kt < 4; kt++) {
            uint32_t vb[5][4];
            #pragma unroll
            for (int p = 0; p < 5; p++)
                ldsm_x4(vb[p], smem_to_u32(&VT[p * 16 + ((lane >> 4) << 3) + (lane & 7)]
                                             [kt * 16 + ((lane >> 3) & 1) * 8]));
            #pragma unroll
            for (int mt = 0; mt < 2; mt++) {
                uint32_t ap[4];
                __half2 p0 = __floats2half2_rn(s[mt][2 * kt][0],     s[mt][2 * kt][1]);
                __half2 p1 = __floats2half2_rn(s[mt][2 * kt][2],     s[mt][2 * kt][3]);
                __half2 p2 = __floats2half2_rn(s[mt][2 * kt + 1][0], s[mt][2 * kt + 1][1]);
                __half2 p3 = __floats2half2_rn(s[mt][2 * kt + 1][2], s[mt][2 * kt + 1][3]);
                ap[0] = *(uint32_t*)&p0; ap[1] = *(uint32_t*)&p1;
                ap[2] = *(uint32_t*)&p2; ap[3] = *(uint32_t*)&p3;
                #pragma unroll
                for (int nt = 0; nt < 10; nt++)
                    mma16816(o[mt][nt], ap, vb[nt >> 1][(nt & 1) * 2], vb[nt >> 1][(nt & 1) * 2 + 1]);
            }
        }
    }

    // write O (d < 72 only)
    #pragma unroll
    for (int mt = 0; mt < 2; mt++) {
        #pragma unroll
        for (int ih = 0; ih < 2; ih++) {
            int row = warp * 32 + mt * 16 + (lane >> 2) + ih * 8;
            float inv = 1.f / lrow[mt][ih];
            __half* ob = O + (qrow0 + row) * (size_t)o_ld + hc;
            #pragma unroll
            for (int nt = 0; nt < 9; nt++) {
                int d = nt * 8 + (lane & 3) * 2;
                *(__half2*)(ob + d) = __floats2half2_rn(o[mt][nt][ih * 2] * inv,
                                                        o[mt][nt][ih * 2 + 1] * inv);
            }
        }
    }
}

// ---------------- RoPE in-place on f16 q,k halves ----------------
__global__ void rope_kernel(__half* __restrict__ qkv,
                            const float* __restrict__ cosb, const float* __restrict__ sinb)
{
    int idx = blockIdx.x * blockDim.x + threadIdx.x;
    if (idx >= M_ROWS * NHEADS * 36) return;
    int d2 = idx % 36;
    int h  = (idx / 36) % NHEADS;
    int r  = idx / (36 * NHEADS);
    int t  = (r >> 8) & 15;
    float c = cosb[t * 36 + d2];
    float s = sinb[t * 36 + d2];
    size_t base = (size_t)r * 3456 + h * HD + 2 * d2;
    __half2 q = *(__half2*)(qkv + base);
    float qe = __low2float(q), qo = __high2float(q);
    *(__half2*)(qkv + base) = __floats2half2_rn(qe * c - qo * s, qe * s + qo * c);
    __half2 k = *(__half2*)(qkv + base + 1152);
    float ke = __low2float(k), ko = __high2float(k);
    *(__half2*)(qkv + base + 1152) = __floats2half2_rn(ke * c - ko * s, ke * s + ko * c);
}

// ---------------- temporal causal attention, f16 I/O ----------------
__global__ void temporal_attn_kernel(const __half* __restrict__ qkv, __half* __restrict__ O)
{
    int idx = blockIdx.x * blockDim.x + threadIdx.x;
    int tq = idx & 15;
    int h  = (idx >> 4) & 15;
    int s  = (idx >> 8) & 255;
    int b  = idx >> 16;
    size_t rowq = (size_t)b * N_TOK + (size_t)tq * 256 + s;
    const __half* qp = qkv + rowq * 3456 + h * HD;
    float q[HD];
    #pragma unroll
    for (int d = 0; d < HD; d++) q[d] = __half2float(qp[d]);

    float sc[T_SZ];
    float m = -1e30f;
    #pragma unroll
    for (int tk = 0; tk < T_SZ; tk++) {
        const __half* kp = qkv + ((size_t)b * N_TOK + (size_t)tk * 256 + s) * 3456 + 1152 + h * HD;
        float a = 0.f;
        #pragma unroll
        for (int d = 0; d < HD; d++) a += q[d] * __half2float(kp[d]);
        a *= SCALE_ATTN;
        if (tk > tq) a = -1e30f;
        sc[tk] = a;
        m = fmaxf(m, a);
    }
    float l = 0.f;
    #pragma unroll
    for (int tk = 0; tk < T_SZ; tk++) { sc[tk] = __expf(sc[tk] - m); l += sc[tk]; }
    float inv = 1.f / l;

    __half* op = O + rowq * C_DIM + h * HD;
    #pragma unroll 2
    for (int d = 0; d < HD; d++) {
        float a = 0.f;
        #pragma unroll
        for (int tk = 0; tk < T_SZ; tk++)
            a += sc[tk] * __half2float(qkv[((size_t)b * N_TOK + (size_t)tk * 256 + s) * 3456 + 2304 + h * HD + d]);
        op[d] = __float2half(a * inv);
    }
}

// ---------------- host orchestration ----------------
extern "C" void kernel_launch(void* const* d_in, const int* in_sizes, int n_in,
                              void* d_out, int out_size)
{
    (void)in_sizes; (void)n_in; (void)out_size;
    const float* x_in    = (const float*)d_in[0];
    const float* y_in    = (const float*)d_in[1];
    const float* t_in    = (const float*)d_in[2];
    const float* sstab   = (const float*)d_in[3];
    const float* w_qkv_s = (const float*)d_in[4];
    const float* b_qkv_s = (const float*)d_in[5];
    const float* w_proj_s = (const float*)d_in[6];
    const float* b_proj_s = (const float*)d_in[7];
    const float* w_qkv_t = (const float*)d_in[8];
    const float* b_qkv_t = (const float*)d_in[9];
    const float* w_proj_t = (const float*)d_in[10];
    const float* b_proj_t = (const float*)d_in[11];
    const float* wq_c  = (const float*)d_in[12];
    const float* bq_c  = (const float*)d_in[13];
    const float* wkv_c = (const float*)d_in[14];
    const float* bkv_c = (const float*)d_in[15];
    const float* wo_c  = (const float*)d_in[16];
    const float* bo_c  = (const float*)d_in[17];
    const float* w_fc1 = (const float*)d_in[18];
    const float* b_fc1 = (const float*)d_in[19];
    const float* w_fc2 = (const float*)d_in[20];
    const float* b_fc2 = (const float*)d_in[21];
    const float* f_cos = (const float*)d_in[22];
    const float* f_sin = (const float*)d_in[23];
    float* out = (float*)d_out;

    float* ss;   cudaGetSymbolAddress((void**)&ss, g_ss);
    __half *wt_qkv_s, *wt_proj_s, *wt_qkv_t, *wt_proj_t, *wt_q_c, *wt_kv_c, *wt_wo_c, *wt_fc1, *wt_fc2;
    __half *xm, *xh, *big, *attn, *kvc, *yh;
    cudaGetSymbolAddress((void**)&wt_qkv_s, g_wt_qkv_s);
    cudaGetSymbolAddress((void**)&wt_proj_s, g_wt_proj_s);
    cudaGetSymbolAddress((void**)&wt_qkv_t, g_wt_qkv_t);
    cudaGetSymbolAddress((void**)&wt_proj_t, g_wt_proj_t);
    cudaGetSymbolAddress((void**)&wt_q_c,  g_wt_q_c);
    cudaGetSymbolAddress((void**)&wt_kv_c, g_wt_kv_c);
    cudaGetSymbolAddress((void**)&wt_wo_c, g_wt_wo_c);
    cudaGetSymbolAddress((void**)&wt_fc1,  g_wt_fc1);
    cudaGetSymbolAddress((void**)&wt_fc2,  g_wt_fc2);
    cudaGetSymbolAddress((void**)&xm,   g_xm);
    cudaGetSymbolAddress((void**)&xh,   g_xh);
    cudaGetSymbolAddress((void**)&big,  g_big);
    cudaGetSymbolAddress((void**)&attn, g_attn);
    cudaGetSymbolAddress((void**)&kvc,  g_kvc);
    cudaGetSymbolAddress((void**)&yh,   g_yh);

    const int GEMM_SMEM = 49152;  // 3 stages x (8KB A + 8KB B)
    cudaFuncSetAttribute(hgemm_kernel<0>, cudaFuncAttributeMaxDynamicSharedMemorySize, GEMM_SMEM);
    cudaFuncSetAttribute(hgemm_kernel<1>, cudaFuncAttributeMaxDynamicSharedMemorySize, GEMM_SMEM);
    cudaFuncSetAttribute(hgemm_kernel<2>, cudaFuncAttributeMaxDynamicSharedMemorySize, GEMM_SMEM);
    cudaFuncSetAttribute(hgemm_kernel<3>, cudaFuncAttributeMaxDynamicSharedMemorySize, GEMM_SMEM);
    cudaFuncSetAttribute(mha_kernel, cudaFuncAttributeMaxDynamicSharedMemorySize, MHA_SMEM);

    dim3 tb(32, 8);
    transpose_f2h_kernel<<<dim3(3456 / 32, 1152 / 32), tb>>>(w_qkv_s, wt_qkv_s, 1152, 3456);
    transpose_f2h_kernel<<<dim3(1152 / 32, 1152 / 32), tb>>>(w_proj_s, wt_proj_s, 1152, 1152);
    transpose_f2h_kernel<<<dim3(3456 / 32, 1152 / 32), tb>>>(w_qkv_t, wt_qkv_t, 1152, 3456);
    transpose_f2h_kernel<<<dim3(1152 / 32, 1152 / 32), tb>>>(w_proj_t, wt_proj_t, 1152, 1152);
    transpose_f2h_kernel<<<dim3(1152 / 32, 1152 / 32), tb>>>(wq_c, wt_q_c, 1152, 1152);
    transpose_f2h_kernel<<<dim3(2304 / 32, 1152 / 32), tb>>>(wkv_c, wt_kv_c, 1152, 2304);
    transpose_f2h_kernel<<<dim3(1152 / 32, 1152 / 32), tb>>>(wo_c, wt_wo_c, 1152, 1152);
    transpose_f2h_kernel<<<dim3(4608 / 32, 1152 / 32), tb>>>(w_fc1, wt_fc1, 1152, 4608);
    transpose_f2h_kernel<<<dim3(1152 / 32, 4608 / 32), tb>>>(w_fc2, wt_fc2, 4608, 1152);
    f2h_kernel<<<(480 * 1152 + 255) / 256, 256>>>(y_in, yh, 480 * 1152);

    compute_ss_kernel<<<(B_SZ * SS_STRIDE + 255) / 256, 256>>>(t_in, sstab, ss);
    ln_mod_kernel<<<M_ROWS, 256>>>(x_in, xm, ss, 0, 1);

    // spatial branch
    hgemm_kernel<0><<<dim3(27, 128), 256, GEMM_SMEM>>>(xm, wt_qkv_s, b_qkv_s,
        nullptr, big, M_ROWS, 3456, 1152, nullptr, nullptr);
    mha_kernel<<<dim3(1, 16, 64), 256, MHA_SMEM>>>(
        big, big + 1152, big + 2304, attn, 3456, 3456, 1152, 256, 256, 256);
    hgemm_kernel<1><<<dim3(9, 128), 256, GEMM_SMEM>>>(attn, wt_proj_s, b_proj_s,
        out, xh, M_ROWS, 1152, 1152, x_in, ss + 2 * C_DIM);

    // temporal branch
    hgemm_kernel<0><<<dim3(27, 128), 256, GEMM_SMEM>>>(xh, wt_qkv_t, b_qkv_t,
        nullptr, big, M_ROWS, 3456, 1152, nullptr, nullptr);
    rope_kernel<<<(M_ROWS * NHEADS * 36 + 255) / 256, 256>>>(big, f_cos, f_sin);
    temporal_attn_kernel<<<1024, 256>>>(big, attn);
    hgemm_kernel<1><<<dim3(9, 128), 256, GEMM_SMEM>>>(attn, wt_proj_t, b_proj_t,
        out, xh, M_ROWS, 1152, 1152, out, ss + 2 * C_DIM);

    // cross attention
    hgemm_kernel<0><<<dim3(9, 128), 256, GEMM_SMEM>>>(xh, wt_q_c, bq_c,
        nullptr, xm, M_ROWS, 1152, 1152, nullptr, nullptr);
    hgemm_kernel<0><<<dim3(18, 4), 256, GEMM_SMEM>>>(yh, wt_kv_c, bkv_c,
        nullptr, kvc, 480, 2304, 1152, nullptr, nullptr);
    mha_kernel<<<dim3(16, 16, 4), 256, MHA_SMEM>>>(
        xm, kvc, kvc + 1152, attn, 1152, 2304, 1152, 4096, 120, 120);
    hgemm_kernel<2><<<dim3(9, 128), 256, GEMM_SMEM>>>(attn, wt_wo_c, bo_c,
        out, nullptr, M_ROWS, 1152, 1152, out, nullptr);

    // MLP
    ln_mod_kernel<<<M_ROWS, 256>>>(out, xm, ss, 3, 4);
    hgemm_kernel<3><<<dim3(36, 128), 256, GEMM_SMEM>>>(xm, wt_fc1, b_fc1,
        nullptr, big, M_ROWS, 4608, 1152, nullptr, nullptr);
    hgemm_kernel<1><<<dim3(9, 128), 256, GEMM_SMEM>>>(big, wt_fc2, b_fc2,
        out, nullptr, M_ROWS, 1152, 4608, out, ss + 5 * C_DIM);
}

// round 5
// speedup vs baseline: 5.2926x; 1.1382x over previous
#include <cuda_runtime.h>
#include <cuda_fp16.h>
#include <math.h>
#include <stdint.h>

// ---------------- problem constants ----------------
#define C_DIM   1152
#define NHEADS  16
#define HD      72
#define B_SZ    4
#define T_SZ    16
#define S_SZ    256
#define N_TOK   4096
#define M_ROWS  16384
#define SS_STRIDE 6912
#define SCALE_ATTN 0.11785113019775792f
#define TSEC_STRIDE 18874368u   // 16384 * 1152, section stride in temporal qkv buffer

// ---------------- ptx helpers (sm_80-level; harness targets plain compute_103) ----------------
__device__ __forceinline__ uint32_t smem_to_u32(const void* p) {
    uint32_t a;
    asm("{ .reg .u64 t; cvta.to.shared.u64 t, %1; cvt.u32.u64 %0, t; }" : "=r"(a) : "l"(p));
    return a;
}
__device__ __forceinline__ void cp16(uint32_t saddr, const void* gaddr) {
    asm volatile("cp.async.cg.shared.global [%0], [%1], 16;" :: "r"(saddr), "l"(gaddr));
}
#define CP_COMMIT() asm volatile("cp.async.commit_group;" ::: "memory")
#define CP_WAIT(n)  asm volatile("cp.async.wait_group %0;" :: "n"(n) : "memory")

__device__ __forceinline__ void ldsm_x4(uint32_t* r, uint32_t addr) {
    asm volatile("ldmatrix.sync.aligned.m8n8.x4.shared.b16 {%0,%1,%2,%3}, [%4];"
        : "=r"(r[0]), "=r"(r[1]), "=r"(r[2]), "=r"(r[3]) : "r"(addr));
}
__device__ __forceinline__ void mma16816(float* c, const uint32_t* a, uint32_t b0, uint32_t b1) {
    asm volatile("mma.sync.aligned.m16n8k16.row.col.f32.f16.f16.f32 "
        "{%0,%1,%2,%3}, {%4,%5,%6,%7}, {%8,%9}, {%0,%1,%2,%3};"
        : "+f"(c[0]), "+f"(c[1]), "+f"(c[2]), "+f"(c[3])
        : "r"(a[0]), "r"(a[1]), "r"(a[2]), "r"(a[3]), "r"(b0), "r"(b1));
}

// ---------------- scratch (device globals) ----------------
__device__ __align__(16) __half g_wt_qkv_s[3456 * 1152];
__device__ __align__(16) __half g_wt_proj_s[1152 * 1152];
__device__ __align__(16) __half g_wt_qkv_t[3456 * 1152];
__device__ __align__(16) __half g_wt_proj_t[1152 * 1152];
__device__ __align__(16) __half g_wt_q_c [1152 * 1152];
__device__ __align__(16) __half g_wt_kv_c[2304 * 1152];
__device__ __align__(16) __half g_wt_wo_c[1152 * 1152];
__device__ __align__(16) __half g_wt_fc1 [4608 * 1152];
__device__ __align__(16) __half g_wt_fc2 [1152 * 4608];
__device__ __align__(16) __half g_xm  [(size_t)M_ROWS * 1152];
__device__ __align__(16) __half g_xh  [(size_t)M_ROWS * 1152];
__device__ __align__(16) __half g_big [(size_t)M_ROWS * 4608];
__device__ __align__(16) __half g_attn[(size_t)M_ROWS * 1152];
__device__ __align__(16) __half g_kvc [512 * 2304];
__device__ __align__(16) __half g_yh  [480 * 1152];
__device__ float  g_ss  [B_SZ * SS_STRIDE];

// ---------------- weight transpose+convert: w[K,N] fp32 -> wt[N,K] f16 ----------------
__global__ void transpose_f2h_kernel(const float* __restrict__ w, __half* __restrict__ wt,
                                     int K, int N)
{
    __shared__ float tile[32][33];
    int n0 = blockIdx.x * 32, k0 = blockIdx.y * 32;
    int tx = threadIdx.x, ty = threadIdx.y;
    #pragma unroll
    for (int i = 0; i < 32; i += 8)
        tile[ty + i][tx] = w[(size_t)(k0 + ty + i) * N + n0 + tx];
    __syncthreads();
    #pragma unroll
    for (int i = 0; i < 32; i += 8)
        wt[(size_t)(n0 + ty + i) * K + k0 + tx] = __float2half(tile[tx][ty + i]);
}

__global__ void f2h_kernel(const float* __restrict__ in, __half* __restrict__ out, int n)
{
    int i = blockIdx.x * blockDim.x + threadIdx.x;
    if (i < n) out[i] = __float2half(in[i]);
}

// ---------------- ss = table + t ----------------
__global__ void compute_ss_kernel(const float* __restrict__ t, const float* __restrict__ table,
                                  float* __restrict__ ss)
{
    int idx = blockIdx.x * blockDim.x + threadIdx.x;
    if (idx >= B_SZ * SS_STRIDE) return;
    int b = idx / SS_STRIDE;
    ss[idx] = table[idx - b * SS_STRIDE] + t[idx];
}

// ---------------- layernorm + modulate -> f16 ----------------
__global__ void ln_mod_kernel(const float* __restrict__ X, __half* __restrict__ Y,
                              const float* __restrict__ ss, int shift_idx, int scale_idx)
{
    int row = blockIdx.x;
    int b = row >> 12;
    const float* xp = X + (size_t)row * C_DIM;
    float lsum = 0.f, lsq = 0.f;
    for (int i = threadIdx.x; i < C_DIM; i += 256) {
        float v = xp[i];
        lsum += v; lsq += v * v;
    }
    __shared__ float s_sum[8], s_sq[8];
    int lane = threadIdx.x & 31, warp = threadIdx.x >> 5;
    #pragma unroll
    for (int off = 16; off > 0; off >>= 1) {
        lsum += __shfl_down_sync(0xffffffffu, lsum, off);
        lsq  += __shfl_down_sync(0xffffffffu, lsq,  off);
    }
    if (lane == 0) { s_sum[warp] = lsum; s_sq[warp] = lsq; }
    __syncthreads();
    __shared__ float s_mu, s_rstd;
    if (threadIdx.x == 0) {
        float su = 0.f, sq = 0.f;
        #pragma unroll
        for (int w = 0; w < 8; w++) { su += s_sum[w]; sq += s_sq[w]; }
        float mu = su / (float)C_DIM;
        float var = sq / (float)C_DIM - mu * mu;
        s_mu = mu; s_rstd = rsqrtf(var + 1e-6f);
    }
    __syncthreads();
    float mu = s_mu, rstd = s_rstd;
    const float* sh = ss + (size_t)(b * 6 + shift_idx) * C_DIM;
    const float* sc = ss + (size_t)(b * 6 + scale_idx) * C_DIM;
    __half* yp = Y + (size_t)row * C_DIM;
    for (int i = threadIdx.x; i < C_DIM; i += 256) {
        float v = (xp[i] - mu) * rstd;
        yp[i] = __float2half(v * (1.f + sc[i]) + sh[i]);
    }
}

// ---------------- f16 tensor-core GEMM, BK=64, 3-stage cp.async pipeline ----------------
// Out = A[M,K] @ Wt[N,K]^T + bias ; 128x128 tile.
// smem: 3 stages x (16KB A + 16KB B) = 96KB. Rows are 128B -> full (row&7) XOR swizzle,
// conflict-free ldmatrix.
// EPI 0: OutH = f16(v)
// EPI 1: v = Res + Gate[b,col]*v; Out(fp32)=v; if OutH: OutH=f16(v)
// EPI 2: v = Res + v; Out(fp32)=v
// EPI 3: OutH = f16(gelu_tanh(v))
// EPI 4: temporal qkv scatter: apply RoPE to q,k sections, write [sec][b,s,h][t][d]
template<int EPI>
__global__ __launch_bounds__(256, 2)
void hgemm_kernel(const __half* __restrict__ A, const __half* __restrict__ Wt,
                  const float* __restrict__ bias,
                  float* __restrict__ Out, __half* __restrict__ OutH,
                  int M, int N, int K,
                  const float* __restrict__ Res, const float* __restrict__ Gate,
                  const float* __restrict__ Cos, const float* __restrict__ Sin)
{
    extern __shared__ char gsm[];   // A: 3 x 16KB, then B: 3 x 16KB
    int tid = threadIdx.x;
    int bm = blockIdx.y * 128;
    int bn = blockIdx.x * 128;
    int warp = tid >> 5, lane = tid & 31;
    int wm = warp & 1, wn = warp >> 1;

    uint32_t aB = smem_to_u32(gsm);
    uint32_t bB = aB + 49152;

    int lrow = tid >> 1;            // 0..127
    int lc0 = (tid & 1) * 4;        // chunk base 0 or 4
    int agr = min(bm + lrow, M - 1);
    const __half* agp = A  + (size_t)agr * K + lc0 * 8;
    const __half* bgp = Wt + (size_t)(bn + lrow) * K + lc0 * 8;
    uint32_t sw[4];
    #pragma unroll
    for (int i = 0; i < 4; i++)
        sw[i] = (uint32_t)(lrow * 128 + (((lc0 + i) ^ (lrow & 7)) << 4));

    int numK = K >> 6;

    // prologue: stages 0,1
    #pragma unroll
    for (int i = 0; i < 4; i++) { cp16(aB + sw[i], agp + i * 8); cp16(bB + sw[i], bgp + i * 8); }
    CP_COMMIT();
    #pragma unroll
    for (int i = 0; i < 4; i++) { cp16(aB + 16384 + sw[i], agp + 64 + i * 8); cp16(bB + 16384 + sw[i], bgp + 64 + i * 8); }
    CP_COMMIT();

    float acc[4][4][4];
    #pragma unroll
    for (int i = 0; i < 4; i++)
        #pragma unroll
        for (int j = 0; j < 4; j++)
            #pragma unroll
            for (int k = 0; k < 4; k++) acc[i][j][k] = 0.f;

    for (int kt = 0; kt < numK; kt++) {
        CP_WAIT(1);
        __syncthreads();
        if (kt + 2 < numK) {
            int nb = kt + 2; nb -= (nb / 3) * 3;
            int koff = (kt + 2) * 64;
            uint32_t ab2 = aB + nb * 16384, bb2 = bB + nb * 16384;
            #pragma unroll
            for (int i = 0; i < 4; i++) {
                cp16(ab2 + sw[i], agp + koff + i * 8);
                cp16(bb2 + sw[i], bgp + koff + i * 8);
            }
        }
        CP_COMMIT();

        int cb = kt; cb -= (cb / 3) * 3;
        uint32_t ab = aB + cb * 16384;
        uint32_t bb = bB + cb * 16384;
        #pragma unroll
        for (int kk = 0; kk < 4; kk++) {
            uint32_t a[4][4];
            #pragma unroll
            for (int mt = 0; mt < 4; mt++) {
                int row = wm * 64 + mt * 16 + (lane & 15);
                int c = kk * 2 + (lane >> 4);
                ldsm_x4(a[mt], ab + row * 128 + ((c ^ (row & 7)) << 4));
            }
            uint32_t b[2][4];
            #pragma unroll
            for (int p = 0; p < 2; p++) {
                int row = wn * 32 + p * 16 + ((lane >> 4) << 3) + (lane & 7);
                int c = kk * 2 + ((lane >> 3) & 1);
                ldsm_x4(b[p], bb + row * 128 + ((c ^ (row & 7)) << 4));
            }
            #pragma unroll
            for (int mt = 0; mt < 4; mt++)
                #pragma unroll
                for (int nt = 0; nt < 4; nt++)
                    mma16816(acc[mt][nt], a[mt], b[nt >> 1][(nt & 1) * 2], b[nt >> 1][(nt & 1) * 2 + 1]);
        }
    }

    // epilogue
    bool hasH = (OutH != nullptr);
    #pragma unroll
    for (int mt = 0; mt < 4; mt++) {
        #pragma unroll
        for (int i = 0; i < 2; i++) {
            int row = bm + wm * 64 + mt * 16 + (lane >> 2) + i * 8;
            if (row >= M) continue;
            size_t orow = (size_t)row * N;
            int b6 = (row >> 12) * SS_STRIDE;
            #pragma unroll
            for (int nt = 0; nt < 4; nt++) {
                int col = bn + wn * 32 + nt * 8 + ((lane & 3) << 1);
                float v0 = acc[mt][nt][i * 2]     + bias[col];
                float v1 = acc[mt][nt][i * 2 + 1] + bias[col + 1];
                size_t o = orow + col;
                if (EPI == 0) {
                    *(__half2*)(OutH + o) = __floats2half2_rn(v0, v1);
                } else if (EPI == 1) {
                    v0 = Res[o]     + Gate[b6 + col]     * v0;
                    v1 = Res[o + 1] + Gate[b6 + col + 1] * v1;
                    *(float2*)(Out + o) = make_float2(v0, v1);
                    if (hasH) *(__half2*)(OutH + o) = __floats2half2_rn(v0, v1);
                } else if (EPI == 2) {
                    v0 += Res[o]; v1 += Res[o + 1];
                    *(float2*)(Out + o) = make_float2(v0, v1);
                } else if (EPI == 3) {
                    float t0 = v0 + 0.044715f * v0 * v0 * v0;
                    float t1 = v1 + 0.044715f * v1 * v1 * v1;
                    float gg0 = 0.5f * v0 * (1.f + tanhf(0.79788456080286536f * t0));
                    float gg1 = 0.5f * v1 * (1.f + tanhf(0.79788456080286536f * t1));
                    *(__half2*)(OutH + o) = __floats2half2_rn(gg0, gg1);
                } else {
                    // EPI 4: temporal scatter + fused RoPE
                    int b = row >> 12, t = (row >> 8) & 15, s = row & 255;
                    int sec = col / 1152;
                    int cc = col - sec * 1152;
                    int h = cc / 72;
                    int d = cc - h * 72;
                    if (sec < 2) {
                        int d2 = d >> 1;
                        float cf = __ldg(Cos + t * 36 + d2);
                        float sf = __ldg(Sin + t * 36 + d2);
                        float e = v0, od = v1;
                        v0 = e * cf - od * sf;
                        v1 = e * sf + od * cf;
                    }
                    size_t dst = (size_t)sec * TSEC_STRIDE
                               + ((size_t)(((b << 8) | s) << 4) + h) * 1152 + t * 72 + d;
                    *(__half2*)(OutH + dst) = __floats2half2_rn(v0, v1);
                }
            }
        }
    }
}

// ---------------- mma flash attention (non-causal), f16 I/O ----------------
// Block: 256 q rows x 1 head. KV chunks of 64. 8 warps, each 32 q rows.
#define MHA_SMEM (256*88*2 + 64*88*2 + 80*72*2)
__global__ __launch_bounds__(256, 1)
void mha_kernel(const __half* __restrict__ Q, const __half* __restrict__ K,
                const __half* __restrict__ V, __half* __restrict__ O,
                int q_ld, int kv_ld, int o_ld,
                int q_us, int kv_us, int kv_len)
{
    extern __shared__ char gsm[];
    __half (*QS)[88] = (__half(*)[88])gsm;
    __half (*KS)[88] = (__half(*)[88])(gsm + 256 * 88 * 2);
    __half (*VT)[72] = (__half(*)[72])(gsm + 256 * 88 * 2 + 64 * 88 * 2);

    int tid = threadIdx.x, warp = tid >> 5, lane = tid & 31;
    int u = blockIdx.z, h = blockIdx.y, qt = blockIdx.x;
    size_t qrow0 = (size_t)u * q_us + (size_t)qt * 256;
    size_t kvrow0 = (size_t)u * kv_us;
    int hc = h * HD;

    {
        const uint2* src = (const uint2*)(Q + (qrow0 + tid) * q_ld + hc);
        uint2* dst = (uint2*)&QS[tid][0];
        #pragma unroll
        for (int i = 0; i < 18; i++) dst[i] = src[i];
        dst[18] = make_uint2(0, 0);
        dst[19] = make_uint2(0, 0);
    }

    float mrow[2][2] = {{-1e30f, -1e30f}, {-1e30f, -1e30f}};
    float lrow[2][2] = {{0.f, 0.f}, {0.f, 0.f}};
    float o[2][10][4];
    #pragma unroll
    for (int mt = 0; mt < 2; mt++)
        #pragma unroll
        for (int nt = 0; nt < 10; nt++)
            #pragma unroll
            for (int j = 0; j < 4; j++) o[mt][nt][j] = 0.f;

    int nchunk = (kv_len + 63) >> 6;
    for (int jc = 0; jc < nchunk; jc++) {
        int j0 = jc * 64;
        __syncthreads();

        for (int idx = tid; idx < 64 * 22; idx += 256) {
            int row = idx / 22, c = idx % 22;
            uint2 val = make_uint2(0, 0);
            int gj = j0 + row;
            if (gj < kv_len && c < 18)
                val = *(const uint2*)(K + (kvrow0 + gj) * kv_ld + hc + c * 4);
            *(uint2*)&KS[row][c * 4] = val;
        }
        for (int idx = tid; idx < 64 * 18; idx += 256) {
            int row = idx / 18, c = idx % 18;
            uint2 val = make_uint2(0, 0);
            int gj = j0 + row;
            if (gj < kv_len)
                val = *(const uint2*)(V + (kvrow0 + gj) * kv_ld + hc + c * 4);
            __half2 v01 = *(__half2*)&val.x;
            __half2 v23 = *(__half2*)&val.y;
            VT[c * 4 + 0][row] = __low2half(v01);
            VT[c * 4 + 1][row] = __high2half(v01);
            VT[c * 4 + 2][row] = __low2half(v23);
            VT[c * 4 + 3][row] = __high2half(v23);
        }
        for (int idx = tid; idx < 8 * 64; idx += 256) {
            VT[72 + idx / 64][idx % 64] = __float2half(0.f);
        }
        __syncthreads();

        float s[2][8][4];
        #pragma unroll
        for (int mt = 0; mt < 2; mt++)
            #pragma unroll
            for (int nt = 0; nt < 8; nt++)
                #pragma unroll
                for (int j = 0; j < 4; j++) s[mt][nt][j] = 0.f;

        #pragma unroll
        for (int kt = 0; kt < 5; kt++) {
            uint32_t a[2][4];
            #pragma unroll
            for (int mt = 0; mt < 2; mt++)
                ldsm_x4(a[mt], smem_to_u32(&QS[warp * 32 + mt * 16 + (lane & 15)]
                                             [kt * 16 + (lane >> 4) * 8]));
            uint32_t kb[4][4];
            #pragma unroll
            for (int p = 0; p < 4; p++)
                ldsm_x4(kb[p], smem_to_u32(&KS[p * 16 + ((lane >> 4) << 3) + (lane & 7)]
                                             [kt * 16 + ((lane >> 3) & 1) * 8]));
            #pragma unroll
            for (int mt = 0; mt < 2; mt++)
                #pragma unroll
                for (int nt = 0; nt < 8; nt++)
                    mma16816(s[mt][nt], a[mt], kb[nt >> 1][(nt & 1) * 2], kb[nt >> 1][(nt & 1) * 2 + 1]);
        }

        #pragma unroll
        for (int mt = 0; mt < 2; mt++) {
            #pragma unroll
            for (int ih = 0; ih < 2; ih++) {
                float rm = -1e30f;
                #pragma unroll
                for (int nt = 0; nt < 8; nt++) {
                    #pragma unroll
                    for (int jj = 0; jj < 2; jj++) {
                        float v = s[mt][nt][ih * 2 + jj] * SCALE_ATTN;
                        int col = j0 + nt * 8 + (lane & 3) * 2 + jj;
                        if (col >= kv_len) v = -1e30f;
                        s[mt][nt][ih * 2 + jj] = v;
                        rm = fmaxf(rm, v);
                    }
                }
                rm = fmaxf(rm, __shfl_xor_sync(0xffffffffu, rm, 1));
                rm = fmaxf(rm, __shfl_xor_sync(0xffffffffu, rm, 2));
                float mn = fmaxf(mrow[mt][ih], rm);
                float corr = __expf(mrow[mt][ih] - mn);
                mrow[mt][ih] = mn;
                float ls = 0.f;
                #pragma unroll
                for (int nt = 0; nt < 8; nt++) {
                    #pragma unroll
                    for (int jj = 0; jj < 2; jj++) {
                        float p = __expf(s[mt][nt][ih * 2 + jj] - mn);
                        s[mt][nt][ih * 2 + jj] = p;
                        ls += p;
                    }
                }
                ls += __shfl_xor_sync(0xffffffffu, ls, 1);
                ls += __shfl_xor_sync(0xffffffffu, ls, 2);
                lrow[mt][ih] = lrow[mt][ih] * corr + ls;
                #pragma unroll
                for (int nt = 0; nt < 10; nt++) {
                    o[mt][nt][ih * 2]     *= corr;
                    o[mt][nt][ih * 2 + 1] *= corr;
                }
            }
        }

        #pragma unroll
        for (int kt = 0; kt < 4; kt++) {
            uint32_t vb[5][4];
            #pragma unroll
            for (int p = 0; p < 5; p++)
                ldsm_x4(vb[p], smem_to_u32(&VT[p * 16 + ((lane >> 4) << 3) + (lane & 7)]
                                             [kt * 16 + ((lane >> 3) & 1) * 8]));
            #pragma unroll
            for (int mt = 0; mt < 2; mt++) {
                uint32_t ap[4];
                __half2 p0 = __floats2half2_rn(s[mt][2 * kt][0],     s[mt][2 * kt][1]);
                __half2 p1 = __floats2half2_rn(s[mt][2 * kt][2],     s[mt][2 * kt][3]);
                __half2 p2 = __floats2half2_rn(s[mt][2 * kt + 1][0], s[mt][2 * kt + 1][1]);
                __half2 p3 = __floats2half2_rn(s[mt][2 * kt + 1][2], s[mt][2 * kt + 1][3]);
                ap[0] = *(uint32_t*)&p0; ap[1] = *(uint32_t*)&p1;
                ap[2] = *(uint32_t*)&p2; ap[3] = *(uint32_t*)&p3;
                #pragma unroll
                for (int nt = 0; nt < 10; nt++)
                    mma16816(o[mt][nt], ap, vb[nt >> 1][(nt & 1) * 2], vb[nt >> 1][(nt & 1) * 2 + 1]);
            }
        }
    }

    #pragma unroll
    for (int mt = 0; mt < 2; mt++) {
        #pragma unroll
        for (int ih = 0; ih < 2; ih++) {
            int row = warp * 32 + mt * 16 + (lane >> 2) + ih * 8;
            float inv = 1.f / lrow[mt][ih];
            __half* ob = O + (qrow0 + row) * (size_t)o_ld + hc;
            #pragma unroll
            for (int nt = 0; nt < 9; nt++) {
                int d = nt * 8 + (lane & 3) * 2;
                *(__half2*)(ob + d) = __floats2half2_rn(o[mt][nt][ih * 2] * inv,
                                                        o[mt][nt][ih * 2 + 1] * inv);
            }
        }
    }
}

// ---------------- temporal causal attention: one warp per (b,s,h) slice, mma ----------------
// qkv in [sec][ (b*256+s)*16+h ][t][d] layout (from EPI 4). Output to token-row layout.
#define TMP_SMEM (8 * (16*88 + 16*88 + 80*24) * 2)
__global__ __launch_bounds__(256)
void temporal_mma_kernel(const __half* __restrict__ QKV, __half* __restrict__ O)
{
    extern __shared__ char gsm[];
    int tid = threadIdx.x, warp = tid >> 5, lane = tid & 31;
    __half* wbase = (__half*)gsm + warp * 4736;
    __half (*sQ)[88] = (__half(*)[88])wbase;
    __half (*sK)[88] = (__half(*)[88])(wbase + 1408);
    __half (*sV)[24] = (__half(*)[24])(wbase + 2816);

    int slice = blockIdx.x * 8 + warp;      // 16384 slices
    int h = slice & 15;
    int bs = slice >> 4;
    int s = bs & 255;
    int b = bs >> 8;

    const __half* qp = QKV + (size_t)slice * 1152;
    const __half* kp = qp + TSEC_STRIDE;
    const __half* vp = qp + 2u * TSEC_STRIDE;

    // load Q,K (coalesced uint2), zero-pad cols 72..79
    for (int i = lane; i < 288; i += 32) {
        int t = i / 18, d4 = (i % 18) * 4;
        *(uint2*)&sQ[t][d4] = *(const uint2*)(qp + t * 72 + d4);
        *(uint2*)&sK[t][d4] = *(const uint2*)(kp + t * 72 + d4);
    }
    if (lane < 16) {
        *(uint4*)&sQ[lane][72] = make_uint4(0, 0, 0, 0);
        *(uint4*)&sK[lane][72] = make_uint4(0, 0, 0, 0);
    }
    // load V transposed: sV[d][t]
    for (int i = lane; i < 16 * 72; i += 32) {
        int t = i / 72, d = i % 72;
        sV[d][t] = vp[i];
    }
    for (int i = lane; i < 8 * 16; i += 32)
        sV[72 + (i >> 4)][i & 15] = __float2half(0.f);
    __syncwarp();

    // S = Q @ K^T  (16x16, k=80)
    float sc[2][4] = {{0.f, 0.f, 0.f, 0.f}, {0.f, 0.f, 0.f, 0.f}};
    #pragma unroll
    for (int kt = 0; kt < 5; kt++) {
        uint32_t a[4], kb[4];
        ldsm_x4(a, smem_to_u32(&sQ[lane & 15][kt * 16 + (lane >> 4) * 8]));
        ldsm_x4(kb, smem_to_u32(&sK[((lane >> 4) << 3) + (lane & 7)][kt * 16 + ((lane >> 3) & 1) * 8]));
        mma16816(sc[0], a, kb[0], kb[1]);
        mma16816(sc[1], a, kb[2], kb[3]);
    }

    // causal softmax (full, single chunk)
    float inv_l[2];
    #pragma unroll
    for (int ih = 0; ih < 2; ih++) {
        int tq = (lane >> 2) + ih * 8;
        float rm = -1e30f;
        #pragma unroll
        for (int nt = 0; nt < 2; nt++)
            #pragma unroll
            for (int jj = 0; jj < 2; jj++) {
                int tk = nt * 8 + (lane & 3) * 2 + jj;
                float v = sc[nt][ih * 2 + jj] * SCALE_ATTN;
                if (tk > tq) v = -1e30f;
                sc[nt][ih * 2 + jj] = v;
                rm = fmaxf(rm, v);
            }
        rm = fmaxf(rm, __shfl_xor_sync(0xffffffffu, rm, 1));
        rm = fmaxf(rm, __shfl_xor_sync(0xffffffffu, rm, 2));
        float ls = 0.f;
        #pragma unroll
        for (int nt = 0; nt < 2; nt++)
            #pragma unroll
            for (int jj = 0; jj < 2; jj++) {
                float p = __expf(sc[nt][ih * 2 + jj] - rm);
                sc[nt][ih * 2 + jj] = p;
                ls += p;
            }
        ls += __shfl_xor_sync(0xffffffffu, ls, 1);
        ls += __shfl_xor_sync(0xffffffffu, ls, 2);
        inv_l[ih] = 1.f / ls;
    }

    // P -> A frag
    uint32_t ap[4];
    __half2 p0 = __floats2half2_rn(sc[0][0], sc[0][1]);
    __half2 p1 = __floats2half2_rn(sc[0][2], sc[0][3]);
    __half2 p2 = __floats2half2_rn(sc[1][0], sc[1][1]);
    __half2 p3 = __floats2half2_rn(sc[1][2], sc[1][3]);
    ap[0] = *(uint32_t*)&p0; ap[1] = *(uint32_t*)&p1;
    ap[2] = *(uint32_t*)&p2; ap[3] = *(uint32_t*)&p3;

    // O = P @ V  (16 x 72, k=16)
    float o[9][4];
    #pragma unroll
    for (int nt = 0; nt < 9; nt++)
        #pragma unroll
        for (int j = 0; j < 4; j++) o[nt][j] = 0.f;
    uint32_t vb[5][4];
    #pragma unroll
    for (int p = 0; p < 5; p++)
        ldsm_x4(vb[p], smem_to_u32(&sV[p * 16 + ((lane >> 4) << 3) + (lane & 7)][((lane >> 3) & 1) * 8]));
    #pragma unroll
    for (int nt = 0; nt < 9; nt++)
        mma16816(o[nt], ap, vb[nt >> 1][(nt & 1) * 2], vb[nt >> 1][(nt & 1) * 2 + 1]);

    // write O to token-row layout
    #pragma unroll
    for (int ih = 0; ih < 2; ih++) {
        int tq = (lane >> 2) + ih * 8;
        size_t rowtok = (size_t)b * N_TOK + (size_t)tq * 256 + s;
        __half* ob = O + rowtok * C_DIM + h * HD;
        float inv = inv_l[ih];
        #pragma unroll
        for (int nt = 0; nt < 9; nt++) {
            int d = nt * 8 + (lane & 3) * 2;
            *(__half2*)(ob + d) = __floats2half2_rn(o[nt][ih * 2] * inv, o[nt][ih * 2 + 1] * inv);
        }
    }
}

// ---------------- host orchestration ----------------
extern "C" void kernel_launch(void* const* d_in, const int* in_sizes, int n_in,
                              void* d_out, int out_size)
{
    (void)in_sizes; (void)n_in; (void)out_size;
    const float* x_in    = (const float*)d_in[0];
    const float* y_in    = (const float*)d_in[1];
    const float* t_in    = (const float*)d_in[2];
    const float* sstab   = (const float*)d_in[3];
    const float* w_qkv_s = (const float*)d_in[4];
    const float* b_qkv_s = (const float*)d_in[5];
    const float* w_proj_s = (const float*)d_in[6];
    const float* b_proj_s = (const float*)d_in[7];
    const float* w_qkv_t = (const float*)d_in[8];
    const float* b_qkv_t = (const float*)d_in[9];
    const float* w_proj_t = (const float*)d_in[10];
    const float* b_proj_t = (const float*)d_in[11];
    const float* wq_c  = (const float*)d_in[12];
    const float* bq_c  = (const float*)d_in[13];
    const float* wkv_c = (const float*)d_in[14];
    const float* bkv_c = (const float*)d_in[15];
    const float* wo_c  = (const float*)d_in[16];
    const float* bo_c  = (const float*)d_in[17];
    const float* w_fc1 = (const float*)d_in[18];
    const float* b_fc1 = (const float*)d_in[19];
    const float* w_fc2 = (const float*)d_in[20];
    const float* b_fc2 = (const float*)d_in[21];
    const float* f_cos = (const float*)d_in[22];
    const float* f_sin = (const float*)d_in[23];
    float* out = (float*)d_out;

    float* ss;   cudaGetSymbolAddress((void**)&ss, g_ss);
    __half *wt_qkv_s, *wt_proj_s, *wt_qkv_t, *wt_proj_t, *wt_q_c, *wt_kv_c, *wt_wo_c, *wt_fc1, *wt_fc2;
    __half *xm, *xh, *big, *attn, *kvc, *yh;
    cudaGetSymbolAddress((void**)&wt_qkv_s, g_wt_qkv_s);
    cudaGetSymbolAddress((void**)&wt_proj_s, g_wt_proj_s);
    cudaGetSymbolAddress((void**)&wt_qkv_t, g_wt_qkv_t);
    cudaGetSymbolAddress((void**)&wt_proj_t, g_wt_proj_t);
    cudaGetSymbolAddress((void**)&wt_q_c,  g_wt_q_c);
    cudaGetSymbolAddress((void**)&wt_kv_c, g_wt_kv_c);
    cudaGetSymbolAddress((void**)&wt_wo_c, g_wt_wo_c);
    cudaGetSymbolAddress((void**)&wt_fc1,  g_wt_fc1);
    cudaGetSymbolAddress((void**)&wt_fc2,  g_wt_fc2);
    cudaGetSymbolAddress((void**)&xm,   g_xm);
    cudaGetSymbolAddress((void**)&xh,   g_xh);
    cudaGetSymbolAddress((void**)&big,  g_big);
    cudaGetSymbolAddress((void**)&attn, g_attn);
    cudaGetSymbolAddress((void**)&kvc,  g_kvc);
    cudaGetSymbolAddress((void**)&yh,   g_yh);

    const int GEMM_SMEM = 98304;  // 3 stages x (16KB A + 16KB B)
    cudaFuncSetAttribute(hgemm_kernel<0>, cudaFuncAttributeMaxDynamicSharedMemorySize, GEMM_SMEM);
    cudaFuncSetAttribute(hgemm_kernel<1>, cudaFuncAttributeMaxDynamicSharedMemorySize, GEMM_SMEM);
    cudaFuncSetAttribute(hgemm_kernel<2>, cudaFuncAttributeMaxDynamicSharedMemorySize, GEMM_SMEM);
    cudaFuncSetAttribute(hgemm_kernel<3>, cudaFuncAttributeMaxDynamicSharedMemorySize, GEMM_SMEM);
    cudaFuncSetAttribute(hgemm_kernel<4>, cudaFuncAttributeMaxDynamicSharedMemorySize, GEMM_SMEM);
    cudaFuncSetAttribute(mha_kernel, cudaFuncAttributeMaxDynamicSharedMemorySize, MHA_SMEM);
    cudaFuncSetAttribute(temporal_mma_kernel, cudaFuncAttributeMaxDynamicSharedMemorySize, TMP_SMEM);

    dim3 tb(32, 8);
    transpose_f2h_kernel<<<dim3(3456 / 32, 1152 / 32), tb>>>(w_qkv_s, wt_qkv_s, 1152, 3456);
    transpose_f2h_kernel<<<dim3(1152 / 32, 1152 / 32), tb>>>(w_proj_s, wt_proj_s, 1152, 1152);
    transpose_f2h_kernel<<<dim3(3456 / 32, 1152 / 32), tb>>>(w_qkv_t, wt_qkv_t, 1152, 3456);
    transpose_f2h_kernel<<<dim3(1152 / 32, 1152 / 32), tb>>>(w_proj_t, wt_proj_t, 1152, 1152);
    transpose_f2h_kernel<<<dim3(1152 / 32, 1152 / 32), tb>>>(wq_c, wt_q_c, 1152, 1152);
    transpose_f2h_kernel<<<dim3(2304 / 32, 1152 / 32), tb>>>(wkv_c, wt_kv_c, 1152, 2304);
    transpose_f2h_kernel<<<dim3(1152 / 32, 1152 / 32), tb>>>(wo_c, wt_wo_c, 1152, 1152);
    transpose_f2h_kernel<<<dim3(4608 / 32, 1152 / 32), tb>>>(w_fc1, wt_fc1, 1152, 4608);
    transpose_f2h_kernel<<<dim3(1152 / 32, 4608 / 32), tb>>>(w_fc2, wt_fc2, 4608, 1152);
    f2h_kernel<<<(480 * 1152 + 255) / 256, 256>>>(y_in, yh, 480 * 1152);

    compute_ss_kernel<<<(B_SZ * SS_STRIDE + 255) / 256, 256>>>(t_in, sstab, ss);
    ln_mod_kernel<<<M_ROWS, 256>>>(x_in, xm, ss, 0, 1);

    // spatial branch
    hgemm_kernel<0><<<dim3(27, 128), 256, GEMM_SMEM>>>(xm, wt_qkv_s, b_qkv_s,
        nullptr, big, M_ROWS, 3456, 1152, nullptr, nullptr, nullptr, nullptr);
    mha_kernel<<<dim3(1, 16, 64), 256, MHA_SMEM>>>(
        big, big + 1152, big + 2304, attn, 3456, 3456, 1152, 256, 256, 256);
    hgemm_kernel<1><<<dim3(9, 128), 256, GEMM_SMEM>>>(attn, wt_proj_s, b_proj_s,
        out, xh, M_ROWS, 1152, 1152, x_in, ss + 2 * C_DIM, nullptr, nullptr);

    // temporal branch: qkv GEMM with fused RoPE + scatter, then warp-mma causal attn
    hgemm_kernel<4><<<dim3(27, 128), 256, GEMM_SMEM>>>(xh, wt_qkv_t, b_qkv_t,
        nullptr, big, M_ROWS, 3456, 1152, nullptr, nullptr, f_cos, f_sin);
    temporal_mma_kernel<<<2048, 256, TMP_SMEM>>>(big, attn);
    hgemm_kernel<1><<<dim3(9, 128), 256, GEMM_SMEM>>>(attn, wt_proj_t, b_proj_t,
        out, xh, M_ROWS, 1152, 1152, out, ss + 2 * C_DIM, nullptr, nullptr);

    // cross attention
    hgemm_kernel<0><<<dim3(9, 128), 256, GEMM_SMEM>>>(xh, wt_q_c, bq_c,
        nullptr, xm, M_ROWS, 1152, 1152, nullptr, nullptr, nullptr, nullptr);
    hgemm_kernel<0><<<dim3(18, 4), 256, GEMM_SMEM>>>(yh, wt_kv_c, bkv_c,
        nullptr, kvc, 480, 2304, 1152, nullptr, nullptr, nullptr, nullptr);
    mha_kernel<<<dim3(16, 16, 4), 256, MHA_SMEM>>>(
        xm, kvc, kvc + 1152, attn, 1152, 2304, 1152, 4096, 120, 120);
    hgemm_kernel<2><<<dim3(9, 128), 256, GEMM_SMEM>>>(attn, wt_wo_c, bo_c,
        out, nullptr, M_ROWS, 1152, 1152, out, nullptr, nullptr, nullptr);

    // MLP
    ln_mod_kernel<<<M_ROWS, 256>>>(out, xm, ss, 3, 4);
    hgemm_kernel<3><<<dim3(36, 128), 256, GEMM_SMEM>>>(xm, wt_fc1, b_fc1,
        nullptr, big, M_ROWS, 4608, 1152, nullptr, nullptr, nullptr, nullptr);
    hgemm_kernel<1><<<dim3(9, 128), 256, GEMM_SMEM>>>(big, wt_fc2, b_fc2,
        out, nullptr, M_ROWS, 1152, 4608, out, ss + 5 * C_DIM, nullptr, nullptr);
}